// round 1
// baseline (speedup 1.0000x reference)
#include <cuda_runtime.h>

#define BATCH 4
#define C 192
#define HW 256
#define HO 128
#define NPIX (HO*HO)      // 16384
#define NPIXF (HW*HW)     // 65536
#define HEADS 8
#define CQH 24
#define CAH 12
#define CA 96

// ---------------- scratch (device statics: allocation-free) ----------------
__device__ float g_q[BATCH*C*NPIX];
__device__ float g_k[BATCH*C*NPIX];
__device__ float g_adw[BATCH*C*NPIX];
__device__ float g_a[BATCH*CA*NPIX];
__device__ float g_v[(size_t)BATCH*C*NPIXF];
__device__ float g_invn_q[BATCH*C];
__device__ float g_invn_k[BATCH*C];
__device__ float g_invn_a[BATCH*CA];
__device__ float g_attn_a[BATCH*HEADS*CQH*CAH];
__device__ float g_attn_k[BATCH*HEADS*CAH*CQH];
__device__ float g_weff[BATCH*C*C];

// ---------------- 1) depthwise stride-2 convs: q and a_dw (share x reads) ---
__global__ __launch_bounds__(256) void dw_kernel(const float* __restrict__ x,
                                                 const float* __restrict__ wq,
                                                 const float* __restrict__ wadw)
{
    int bc = blockIdx.y;            // b*C + c
    int c  = bc % C;
    int pix = blockIdx.x * 256 + threadIdx.x;   // 0..NPIX-1
    int oy = pix >> 7, ox = pix & 127;
    const float* xp = x + (size_t)bc * NPIXF;
    float wqr[9], war[9];
#pragma unroll
    for (int i = 0; i < 9; i++) { wqr[i] = wq[c*9+i]; war[i] = wadw[c*9+i]; }
    float accq = 0.f, acca = 0.f;
#pragma unroll
    for (int ky = 0; ky < 3; ky++) {
        int iy = 2*oy + ky - 1;
        if (iy < 0 || iy >= HW) continue;
#pragma unroll
        for (int kx = 0; kx < 3; kx++) {
            int ix = 2*ox + kx - 1;
            if (ix < 0 || ix >= HW) continue;
            float xv = xp[iy*HW + ix];
            accq = fmaf(wqr[ky*3+kx], xv, accq);
            acca = fmaf(war[ky*3+kx], xv, acca);
        }
    }
    size_t o = (size_t)bc * NPIX + pix;
    g_q[o] = accq;
    g_adw[o] = acca;
}

// ---------------- 2) full 3x3 stride-2 conv: k (192->192) -------------------
// block: 32x32 output pixels, 8 output channels; thread: 2x2 px * 8 oc
__global__ __launch_bounds__(256) void kconv_kernel(const float* __restrict__ x,
                                                    const float* __restrict__ wk)
{
    __shared__ float xs[65*66];
    __shared__ float ws[8*9];
    int bz  = blockIdx.z;
    int b   = bz / 24;
    int ocg = bz % 24;
    int oy0 = blockIdx.y * 32;
    int ox0 = blockIdx.x * 32;
    int iy0 = 2*oy0 - 1, ix0 = 2*ox0 - 1;
    int tid = threadIdx.y * 16 + threadIdx.x;

    float acc[8][2][2];
#pragma unroll
    for (int oc = 0; oc < 8; oc++)
#pragma unroll
        for (int sy = 0; sy < 2; sy++)
#pragma unroll
            for (int sx = 0; sx < 2; sx++) acc[oc][sy][sx] = 0.f;

    for (int ic = 0; ic < C; ic++) {
        const float* xp = x + (size_t)(b*C + ic) * NPIXF;
        for (int i = tid; i < 65*65; i += 256) {
            int r = i / 65, cc = i % 65;
            int iy = iy0 + r, ix = ix0 + cc;
            float v = 0.f;
            if (iy >= 0 && iy < HW && ix >= 0 && ix < HW) v = xp[iy*HW + ix];
            xs[r*66 + cc] = v;
        }
        if (tid < 72) ws[tid] = wk[((ocg*8 + tid/9) * C + ic) * 9 + (tid % 9)];
        __syncthreads();

        float xv[5][5];
        int rb = 4*threadIdx.y, cb = 4*threadIdx.x;
#pragma unroll
        for (int r = 0; r < 5; r++)
#pragma unroll
            for (int cc2 = 0; cc2 < 5; cc2++)
                xv[r][cc2] = xs[(rb+r)*66 + cb + cc2];

#pragma unroll
        for (int oc = 0; oc < 8; oc++) {
            float w[9];
#pragma unroll
            for (int i = 0; i < 9; i++) w[i] = ws[oc*9 + i];
#pragma unroll
            for (int sy = 0; sy < 2; sy++)
#pragma unroll
                for (int sx = 0; sx < 2; sx++) {
                    float s = acc[oc][sy][sx];
#pragma unroll
                    for (int ky = 0; ky < 3; ky++)
#pragma unroll
                        for (int kx = 0; kx < 3; kx++)
                            s = fmaf(w[ky*3+kx], xv[2*sy+ky][2*sx+kx], s);
                    acc[oc][sy][sx] = s;
                }
        }
        __syncthreads();
    }

#pragma unroll
    for (int oc = 0; oc < 8; oc++) {
        int c = ocg*8 + oc;
#pragma unroll
        for (int sy = 0; sy < 2; sy++) {
            int oy = oy0 + 2*threadIdx.y + sy;
#pragma unroll
            for (int sx = 0; sx < 2; sx++) {
                int ox = ox0 + 2*threadIdx.x + sx;
                g_k[(size_t)(b*C + c)*NPIX + oy*HO + ox] = acc[oc][sy][sx];
            }
        }
    }
}

// ---------------- 3) pointwise 192->96 (+bias) on a_dw ----------------------
__global__ __launch_bounds__(256) void apw_kernel(const float* __restrict__ wapw,
                                                  const float* __restrict__ bapw)
{
    __shared__ float s[C*64];     // 48KB
    int b = blockIdx.y;
    int p0 = blockIdx.x * 64;
    for (int i = threadIdx.x; i < C*64; i += 256) {
        int cc = i >> 6, pp = i & 63;
        s[i] = g_adw[(size_t)(b*C + cc)*NPIX + p0 + pp];
    }
    __syncthreads();
    int pg  = threadIdx.x & 15;   // 4-pixel group
    int ocb = threadIdx.x >> 4;   // 0..15
    for (int oc = ocb; oc < CA; oc += 16) {
        float bsv = bapw[oc];
        float4 acc = make_float4(bsv, bsv, bsv, bsv);
        for (int ic = 0; ic < C; ic++) {
            float w = __ldg(&wapw[oc*C + ic]);
            float4 xv = *reinterpret_cast<const float4*>(&s[ic*64 + pg*4]);
            acc.x = fmaf(w, xv.x, acc.x);
            acc.y = fmaf(w, xv.y, acc.y);
            acc.z = fmaf(w, xv.z, acc.z);
            acc.w = fmaf(w, xv.w, acc.w);
        }
        float4* dst = reinterpret_cast<float4*>(&g_a[(size_t)(b*CA + oc)*NPIX + p0 + pg*4]);
        *dst = acc;
    }
}

// ---------------- 4) per-channel inverse L2 norms ---------------------------
__global__ __launch_bounds__(256) void norm_kernel()
{
    __shared__ float red[8];
    int t = blockIdx.x;
    const float* p;
    float* out;
    if (t < BATCH*C)            { p = g_q + (size_t)t*NPIX;              out = &g_invn_q[t]; }
    else if (t < 2*BATCH*C)     { t -= BATCH*C;  p = g_k + (size_t)t*NPIX; out = &g_invn_k[t]; }
    else                        { t -= 2*BATCH*C; p = g_a + (size_t)t*NPIX; out = &g_invn_a[t]; }

    const float4* p4 = reinterpret_cast<const float4*>(p);
    float s = 0.f;
    for (int i = threadIdx.x; i < NPIX/4; i += 256) {
        float4 v = p4[i];
        s += v.x*v.x + v.y*v.y + v.z*v.z + v.w*v.w;
    }
#pragma unroll
    for (int off = 16; off; off >>= 1) s += __shfl_down_sync(0xffffffffu, s, off);
    int warp = threadIdx.x >> 5, lane = threadIdx.x & 31;
    if (lane == 0) red[warp] = s;
    __syncthreads();
    if (threadIdx.x == 0) {
        float tot = 0.f;
        for (int w = 0; w < 8; w++) tot += red[w];
        *out = 1.f / fmaxf(sqrtf(tot), 1e-12f);
    }
}

// ---------------- 5) tiny attention dot products ----------------------------
// blockIdx.y: 0 -> attn_a (q . a), 1 -> attn_k (a . k)
__global__ __launch_bounds__(256) void attn_kernel(const float* __restrict__ ta,
                                                   const float* __restrict__ tv)
{
    __shared__ float red[8][12];
    int mode = blockIdx.y;
    int id = blockIdx.x;
    int c = id % CQH;
    int h = (id / CQH) % HEADS;
    int b = id / (CQH * HEADS);

    const float4* a4 = reinterpret_cast<const float4*>(g_a + (size_t)(b*CA + h*CAH)*NPIX);
    const float4* q4 = reinterpret_cast<const float4*>(
        (mode == 0 ? g_q : g_k) + (size_t)(b*C + h*CQH + c)*NPIX);

    float acc[12];
#pragma unroll
    for (int d = 0; d < 12; d++) acc[d] = 0.f;

    for (int n = threadIdx.x; n < NPIX/4; n += 256) {
        float4 qv = q4[n];
#pragma unroll
        for (int d = 0; d < 12; d++) {
            float4 av = a4[d*(NPIX/4) + n];
            acc[d] += qv.x*av.x + qv.y*av.y + qv.z*av.z + qv.w*av.w;
        }
    }
#pragma unroll
    for (int d = 0; d < 12; d++)
#pragma unroll
        for (int off = 16; off; off >>= 1)
            acc[d] += __shfl_down_sync(0xffffffffu, acc[d], off);
    int warp = threadIdx.x >> 5, lane = threadIdx.x & 31;
    if (lane == 0)
        for (int d = 0; d < 12; d++) red[warp][d] = acc[d];
    __syncthreads();
    if (threadIdx.x < 12) {
        int d = threadIdx.x;
        float s = 0.f;
        for (int w = 0; w < 8; w++) s += red[w][d];
        float inva = g_invn_a[b*CA + h*CAH + d];
        if (mode == 0) {
            float v = s * g_invn_q[b*C + h*CQH + c] * inva * ta[h];
            g_attn_a[((b*HEADS + h)*CQH + c)*CAH + d] = v;
        } else {
            float v = s * g_invn_k[b*C + h*CQH + c] * inva * tv[h];
            g_attn_k[((b*HEADS + h)*CAH + d)*CQH + c] = v;
        }
    }
}

// ---------------- 6) softmaxes, M = SA@SK, W_eff = wo . blockdiag(M) --------
__global__ __launch_bounds__(256) void combine_kernel(const float* __restrict__ wo)
{
    __shared__ float SA[HEADS][CQH][CAH];
    __shared__ float SK[HEADS][CAH][CQH];
    __shared__ float M[HEADS][CQH][CQH];
    int b = blockIdx.x;
    int tid = threadIdx.x;

    if (tid < HEADS*CQH) {            // 192 rows of attn_a, softmax over 12
        int h = tid / CQH, c = tid % CQH;
        const float* row = &g_attn_a[((b*HEADS + h)*CQH + c)*CAH];
        float m = row[0];
        for (int d = 1; d < CAH; d++) m = fmaxf(m, row[d]);
        float s = 0.f, e[CAH];
        for (int d = 0; d < CAH; d++) { e[d] = expf(row[d] - m); s += e[d]; }
        float inv = 1.f / s;
        for (int d = 0; d < CAH; d++) SA[h][c][d] = e[d] * inv;
    }
    if (tid < HEADS*CAH) {            // 96 rows of attn_k, softmax over 24
        int h = tid / CAH, d = tid % CAH;
        const float* row = &g_attn_k[((b*HEADS + h)*CAH + d)*CQH];
        float m = row[0];
        for (int c = 1; c < CQH; c++) m = fmaxf(m, row[c]);
        float s = 0.f, e[CQH];
        for (int c = 0; c < CQH; c++) { e[c] = expf(row[c] - m); s += e[c]; }
        float inv = 1.f / s;
        for (int c = 0; c < CQH; c++) SK[h][d][c] = e[c] * inv;
    }
    __syncthreads();

    for (int i = tid; i < HEADS*CQH*CQH; i += 256) {
        int h = i / (CQH*CQH);
        int r = (i / CQH) % CQH;
        int col = i % CQH;
        float s = 0.f;
#pragma unroll
        for (int d = 0; d < CAH; d++) s = fmaf(SA[h][r][d], SK[h][d][col], s);
        M[h][r][col] = s;
    }
    __syncthreads();

    for (int i = tid; i < C*C; i += 256) {
        int o = i / C, cv = i % C;
        int hv = cv / CQH, j = cv % CQH;
        float s = 0.f;
#pragma unroll
        for (int k = 0; k < CQH; k++)
            s = fmaf(wo[o*C + hv*CQH + k], M[hv][k][j], s);
        g_weff[b*C*C + i] = s;
    }
}

// ---------------- 7/8) SGEMM 192xK x pixels (64x64 tile, 4x4/thread) --------
// MODE 0: C_v = (wv @ x) * illu    -> g_v
// MODE 1: out = W_eff[b] @ g_v     -> Cext
template<int MODE>
__global__ __launch_bounds__(256) void sgemm_kernel(const float* __restrict__ Aext,
                                                    const float* __restrict__ Bext,
                                                    const float* __restrict__ illu,
                                                    float* __restrict__ Cext)
{
    __shared__ float As[8][64];
    __shared__ float Bs[8][64];
    int b  = blockIdx.z;
    int m0 = blockIdx.y * 64;
    int p0 = blockIdx.x * 64;
    const float* A  = (MODE == 0) ? Aext : (g_weff + b*C*C);
    const float* Bb = ((MODE == 0) ? Bext : g_v) + (size_t)b*C*NPIXF;
    float*       Cb = ((MODE == 0) ? g_v  : Cext) + (size_t)b*C*NPIXF;
    const float* Ib = (MODE == 0) ? (illu + (size_t)b*C*NPIXF) : nullptr;

    int tid = threadIdx.x;
    int tx = tid & 15, ty = tid >> 4;
    float acc[4][4];
#pragma unroll
    for (int i = 0; i < 4; i++)
#pragma unroll
        for (int j = 0; j < 4; j++) acc[i][j] = 0.f;

    for (int k0 = 0; k0 < C; k0 += 8) {
        {
            int r = tid >> 3, kk = tid & 7;
            As[kk][r]      = A[(m0 + r)      * C + k0 + kk];
            As[kk][r + 32] = A[(m0 + r + 32) * C + k0 + kk];
        }
        {
            int kk = tid >> 6, nn = tid & 63;
            Bs[kk][nn]     = Bb[(size_t)(k0 + kk)     * NPIXF + p0 + nn];
            Bs[kk + 4][nn] = Bb[(size_t)(k0 + kk + 4) * NPIXF + p0 + nn];
        }
        __syncthreads();
#pragma unroll
        for (int k = 0; k < 8; k++) {
            float4 av = *reinterpret_cast<const float4*>(&As[k][ty*4]);
            float4 bv = *reinterpret_cast<const float4*>(&Bs[k][tx*4]);
            float a[4] = {av.x, av.y, av.z, av.w};
            float bb[4] = {bv.x, bv.y, bv.z, bv.w};
#pragma unroll
            for (int i = 0; i < 4; i++)
#pragma unroll
                for (int j = 0; j < 4; j++)
                    acc[i][j] = fmaf(a[i], bb[j], acc[i][j]);
        }
        __syncthreads();
    }

#pragma unroll
    for (int i = 0; i < 4; i++) {
        int m = m0 + ty*4 + i;
        size_t base = (size_t)m * NPIXF + p0 + tx*4;
        float4 v = make_float4(acc[i][0], acc[i][1], acc[i][2], acc[i][3]);
        if (MODE == 0) {
            float4 il = *reinterpret_cast<const float4*>(&Ib[base]);
            v.x *= il.x; v.y *= il.y; v.z *= il.z; v.w *= il.w;
        }
        *reinterpret_cast<float4*>(&Cb[base]) = v;
    }
}

// ---------------- launch ----------------------------------------------------
extern "C" void kernel_launch(void* const* d_in, const int* in_sizes, int n_in,
                              void* d_out, int out_size)
{
    const float* x    = (const float*)d_in[0];
    const float* illu = (const float*)d_in[1];
    const float* wq   = (const float*)d_in[2];
    const float* wk   = (const float*)d_in[3];
    const float* wadw = (const float*)d_in[4];
    const float* wapw = (const float*)d_in[5];
    const float* bapw = (const float*)d_in[6];
    const float* wv   = (const float*)d_in[7];
    const float* wo   = (const float*)d_in[8];
    const float* ta   = (const float*)d_in[9];
    const float* tv   = (const float*)d_in[10];
    float* out = (float*)d_out;

    dw_kernel   <<<dim3(NPIX/256, BATCH*C), 256>>>(x, wq, wadw);
    kconv_kernel<<<dim3(4, 4, BATCH*24), dim3(16,16)>>>(x, wk);
    apw_kernel  <<<dim3(NPIX/64, BATCH), 256>>>(wapw, bapw);
    norm_kernel <<<BATCH*(C + C + CA), 256>>>();
    attn_kernel <<<dim3(BATCH*HEADS*CQH, 2), 256>>>(ta, tv);
    combine_kernel<<<BATCH, 256>>>(wo);
    sgemm_kernel<0><<<dim3(NPIXF/64, C/64, BATCH), 256>>>(wv, x, illu, nullptr);
    sgemm_kernel<1><<<dim3(NPIXF/64, C/64, BATCH), 256>>>(nullptr, nullptr, nullptr, out);
}

// round 2
// speedup vs baseline: 1.8378x; 1.8378x over previous
#include <cuda_runtime.h>
#include <cstdint>

#define BATCH 4
#define C 192
#define HW 256
#define HO 128
#define NPIX (HO*HO)      // 16384
#define NPIXF (HW*HW)     // 65536
#define HEADS 8
#define CQH 24
#define CAH 12
#define CA 96
#define KKDIM (C*9)       // 1728
#define PLANE (129*132)
#define NSPLIT 8
#define DOTP 640          // 288 dq + 288 dk + 24 qq + 24 kk + 12 aa (padded)

// ---------------- scratch ----------------
__device__ float g_q[BATCH*C*NPIX];
__device__ float g_k[BATCH*C*NPIX];
__device__ float g_adw[BATCH*C*NPIX];
__device__ float g_a[BATCH*CA*NPIX];
__device__ float g_v[(size_t)BATCH*C*NPIXF];
__device__ float g_xp[(size_t)BATCH*C*4*PLANE];
__device__ float g_wkT[KKDIM*C];
__device__ float g_wvT[C*C];
__device__ float g_weffT[BATCH*C*C];
__device__ float g_dotp[(size_t)NSPLIT*BATCH*HEADS*DOTP];

// ---------------- tf32 helpers ----------------
__device__ __forceinline__ unsigned f2tf(float f){
    unsigned r; asm("cvt.rna.tf32.f32 %0, %1;" : "=r"(r) : "f"(f)); return r;
}
__device__ __forceinline__ void mma_tf32(float& c0, float& c1, float& c2, float& c3,
                                         unsigned a0, unsigned a1, unsigned a2, unsigned a3,
                                         unsigned b0, unsigned b1){
    asm volatile("mma.sync.aligned.m16n8k8.row.col.f32.tf32.tf32.f32 "
                 "{%0,%1,%2,%3},{%4,%5,%6,%7},{%8,%9},{%0,%1,%2,%3};"
                 : "+f"(c0), "+f"(c1), "+f"(c2), "+f"(c3)
                 : "r"(a0), "r"(a1), "r"(a2), "r"(a3), "r"(b0), "r"(b1));
}

// ---------------- prep: transpose wk -> [k][oc], wv -> [ic][oc] -------------
__global__ __launch_bounds__(256) void prep_kernel(const float* __restrict__ wk,
                                                   const float* __restrict__ wv)
{
    int i = blockIdx.x * 256 + threadIdx.x;
    if (i < KKDIM*C) {
        int k = i / C, oc = i % C;
        g_wkT[i] = wk[oc*KKDIM + k];
    } else {
        int j = i - KKDIM*C;
        if (j < C*C) {
            int ic = j / C, oc = j % C;
            g_wvT[j] = wv[oc*C + ic];
        }
    }
}

// ---------------- zero pad borders of phase planes --------------------------
__global__ void zeropad_kernel()
{
    size_t base = (size_t)blockIdx.x * PLANE;
    int t = threadIdx.x;
    if (t < 132) g_xp[base + t] = 0.f;
    int r = t - 131;                 // t=132 -> r=1
    if (t >= 132 && r <= 128) g_xp[base + r*132] = 0.f;
}

// ---------------- split x into 4 stride-2 parity planes (padded) ------------
__global__ __launch_bounds__(256) void split_kernel(const float* __restrict__ x)
{
    int bc = blockIdx.y;
    int px = blockIdx.x * 256 + threadIdx.x;
    int iy = px >> 8, ix = px & 255;
    float v = x[(size_t)bc * NPIXF + px];
    int ph = ((iy & 1) << 1) | (ix & 1);
    g_xp[((size_t)bc*4 + ph)*PLANE + ((iy>>1)+1)*132 + (ix>>1) + 1] = v;
}

// ---------------- depthwise stride-2 convs: q and a_dw ----------------------
__global__ __launch_bounds__(256) void dw_kernel(const float* __restrict__ x,
                                                 const float* __restrict__ wq,
                                                 const float* __restrict__ wadw)
{
    int bc = blockIdx.y;
    int c  = bc % C;
    int pix = blockIdx.x * 256 + threadIdx.x;
    int oy = pix >> 7, ox = pix & 127;
    const float* xp = x + (size_t)bc * NPIXF;
    float wqr[9], war[9];
#pragma unroll
    for (int i = 0; i < 9; i++) { wqr[i] = wq[c*9+i]; war[i] = wadw[c*9+i]; }
    float accq = 0.f, acca = 0.f;
#pragma unroll
    for (int ky = 0; ky < 3; ky++) {
        int iy = 2*oy + ky - 1;
        if (iy < 0 || iy >= HW) continue;
#pragma unroll
        for (int kx = 0; kx < 3; kx++) {
            int ix = 2*ox + kx - 1;
            if (ix < 0 || ix >= HW) continue;
            float xv = xp[iy*HW + ix];
            accq = fmaf(wqr[ky*3+kx], xv, accq);
            acca = fmaf(war[ky*3+kx], xv, acca);
        }
    }
    size_t o = (size_t)bc * NPIX + pix;
    g_q[o] = accq;
    g_adw[o] = acca;
}

// ---------------- kconv: tf32 implicit GEMM over parity planes --------------
// tile: 64 oc x 128 px (8 oy x 16 ox), K = 1728 in chunks of 32
__global__ __launch_bounds__(256) void kconv_kernel()
{
    __shared__ unsigned As[32][72];
    __shared__ unsigned Bs[32][136];
    __shared__ int rowoff[32];
    int b = blockIdx.z, mt = blockIdx.y, tile = blockIdx.x;
    int oy0 = (tile >> 3) * 8, ox0 = (tile & 7) * 16;
    int m0 = mt * 64;
    int tid = threadIdx.x;
    int warp = tid >> 5, lane = tid & 31;
    int wm = warp >> 2, wn = warp & 3;
    int g = lane >> 2, tg = lane & 3;

    float acc[2][4][4];
#pragma unroll
    for (int a = 0; a < 2; a++)
#pragma unroll
        for (int bn = 0; bn < 4; bn++)
#pragma unroll
            for (int q = 0; q < 4; q++) acc[a][bn][q] = 0.f;

    for (int k0 = 0; k0 < KKDIM; k0 += 32) {
        __syncthreads();
        if (tid < 32) {
            int k = k0 + tid;
            int ic = k / 9, t = k - ic*9;
            int ky = t / 3, kx = t - ky*3;
            int py = (ky == 1) ? 0 : 1, pxp = (kx == 1) ? 0 : 1;
            int dy = (ky == 0) ? 0 : 1, dx = (kx == 0) ? 0 : 1;
            rowoff[tid] = ((b*C + ic)*4 + py*2 + pxp)*PLANE + (oy0+dy)*132 + (ox0+dx);
        }
        for (int i = tid; i < 512; i += 256) {
            int kk = i >> 4, m4 = (i & 15) * 4;
            float4 v4 = *(const float4*)&g_wkT[(k0+kk)*C + m0 + m4];
            uint4 u = make_uint4(f2tf(v4.x), f2tf(v4.y), f2tf(v4.z), f2tf(v4.w));
            *(uint4*)&As[kk][m4] = u;
        }
        __syncthreads();
        for (int i = tid; i < 4096; i += 256) {
            int kk = i >> 7, cc = i & 127;
            int pr = cc >> 4, pc = cc & 15;
            Bs[kk][cc] = f2tf(__ldg(&g_xp[rowoff[kk] + pr*132 + pc]));
        }
        __syncthreads();
#pragma unroll
        for (int k8 = 0; k8 < 4; k8++) {
            int kb = k8 * 8;
            unsigned a[2][4], bb[4][2];
#pragma unroll
            for (int mf = 0; mf < 2; mf++) {
                int mb = wm*32 + mf*16 + g;
                a[mf][0] = As[kb+tg][mb];     a[mf][1] = As[kb+tg][mb+8];
                a[mf][2] = As[kb+tg+4][mb];   a[mf][3] = As[kb+tg+4][mb+8];
            }
#pragma unroll
            for (int nf = 0; nf < 4; nf++) {
                int nb = wn*32 + nf*8 + g;
                bb[nf][0] = Bs[kb+tg][nb];    bb[nf][1] = Bs[kb+tg+4][nb];
            }
#pragma unroll
            for (int mf = 0; mf < 2; mf++)
#pragma unroll
                for (int nf = 0; nf < 4; nf++)
                    mma_tf32(acc[mf][nf][0], acc[mf][nf][1], acc[mf][nf][2], acc[mf][nf][3],
                             a[mf][0], a[mf][1], a[mf][2], a[mf][3], bb[nf][0], bb[nf][1]);
        }
    }
#pragma unroll
    for (int mf = 0; mf < 2; mf++)
#pragma unroll
        for (int nf = 0; nf < 4; nf++) {
            int m = m0 + wm*32 + mf*16 + g;
            int n = wn*32 + nf*8 + tg*2;
            int oy = oy0 + (n >> 4), ox = ox0 + (n & 15);
            float2 v0 = make_float2(acc[mf][nf][0], acc[mf][nf][1]);
            float2 v1 = make_float2(acc[mf][nf][2], acc[mf][nf][3]);
            *(float2*)&g_k[(size_t)(b*C + m)*NPIX + oy*HO + ox] = v0;
            *(float2*)&g_k[(size_t)(b*C + m + 8)*NPIX + oy*HO + ox] = v1;
        }
}

// ---------------- pointwise 192->96 (+bias) on a_dw -------------------------
__global__ __launch_bounds__(256) void apw_kernel(const float* __restrict__ wapw,
                                                  const float* __restrict__ bapw)
{
    __shared__ float s[C*64];
    int b = blockIdx.y;
    int p0 = blockIdx.x * 64;
    for (int i = threadIdx.x; i < C*64; i += 256) {
        int cc = i >> 6, pp = i & 63;
        s[i] = g_adw[(size_t)(b*C + cc)*NPIX + p0 + pp];
    }
    __syncthreads();
    int pg  = threadIdx.x & 15;
    int ocb = threadIdx.x >> 4;
    for (int oc = ocb; oc < CA; oc += 16) {
        float bsv = bapw[oc];
        float4 acc = make_float4(bsv, bsv, bsv, bsv);
        for (int ic = 0; ic < C; ic++) {
            float w = __ldg(&wapw[oc*C + ic]);
            float4 xv = *reinterpret_cast<const float4*>(&s[ic*64 + pg*4]);
            acc.x = fmaf(w, xv.x, acc.x);
            acc.y = fmaf(w, xv.y, acc.y);
            acc.z = fmaf(w, xv.z, acc.z);
            acc.w = fmaf(w, xv.w, acc.w);
        }
        *reinterpret_cast<float4*>(&g_a[(size_t)(b*CA + oc)*NPIX + p0 + pg*4]) = acc;
    }
}

// ---------------- attention dots + fused norms (split partials) -------------
__global__ __launch_bounds__(768) void attn_kernel()
{
    __shared__ float a_s[CAH][256];
    int split = blockIdx.x, bh = blockIdx.y;
    int b = bh >> 3, h = bh & 7;
    int tid = threadIdx.x, warp = tid >> 5, lane = tid & 31;
    const float* qp = g_q + (size_t)(b*C + h*CQH + warp)*NPIX;
    const float* kp = g_k + (size_t)(b*C + h*CQH + warp)*NPIX;
    const float* ap = g_a + (size_t)(b*CA + h*CAH)*NPIX;
    int p0 = split * (NPIX / NSPLIT);

    float dq[12], dk[12];
#pragma unroll
    for (int d = 0; d < 12; d++) { dq[d] = 0.f; dk[d] = 0.f; }
    float qq = 0.f, kk = 0.f, aa = 0.f;

    for (int c0 = 0; c0 < NPIX/NSPLIT; c0 += 256) {
        for (int i = tid; i < CAH*256; i += 768) {
            int d = i >> 8, p = i & 255;
            a_s[d][p] = ap[(size_t)d*NPIX + p0 + c0 + p];
        }
        __syncthreads();
#pragma unroll
        for (int hf = 0; hf < 2; hf++) {
            int p = hf*128 + lane*4;
            float4 qv = *(const float4*)&qp[p0 + c0 + p];
            float4 kv = *(const float4*)&kp[p0 + c0 + p];
            qq += qv.x*qv.x + qv.y*qv.y + qv.z*qv.z + qv.w*qv.w;
            kk += kv.x*kv.x + kv.y*kv.y + kv.z*kv.z + kv.w*kv.w;
            if (warp < CAH) {
                float4 av = *(const float4*)&a_s[warp][p];
                aa += av.x*av.x + av.y*av.y + av.z*av.z + av.w*av.w;
            }
#pragma unroll
            for (int d = 0; d < 12; d++) {
                float4 av = *(const float4*)&a_s[d][p];
                dq[d] += qv.x*av.x + qv.y*av.y + qv.z*av.z + qv.w*av.w;
                dk[d] += kv.x*av.x + kv.y*av.y + kv.z*av.z + kv.w*av.w;
            }
        }
        __syncthreads();
    }
#pragma unroll
    for (int off = 16; off; off >>= 1) {
#pragma unroll
        for (int d = 0; d < 12; d++) {
            dq[d] += __shfl_down_sync(0xffffffffu, dq[d], off);
            dk[d] += __shfl_down_sync(0xffffffffu, dk[d], off);
        }
        qq += __shfl_down_sync(0xffffffffu, qq, off);
        kk += __shfl_down_sync(0xffffffffu, kk, off);
        aa += __shfl_down_sync(0xffffffffu, aa, off);
    }
    if (lane == 0) {
        float* out = &g_dotp[((size_t)split*BATCH*HEADS + bh)*DOTP];
#pragma unroll
        for (int d = 0; d < 12; d++) {
            out[warp*12 + d]       = dq[d];
            out[288 + warp*12 + d] = dk[d];
        }
        out[576 + warp] = qq;
        out[600 + warp] = kk;
        if (warp < 12) out[624 + warp] = aa;
    }
}

// ---------------- combine: sums, norms, softmax, M, W_eff^T -----------------
__global__ __launch_bounds__(256) void combine_kernel(const float* __restrict__ wo,
                                                      const float* __restrict__ ta,
                                                      const float* __restrict__ tv)
{
    __shared__ float buf[HEADS*DOTP];        // 5120 floats; reused for M later
    __shared__ float SA[HEADS][CQH][CAH];
    __shared__ float SK[HEADS][CAH][CQH];
    int b = blockIdx.x, tid = threadIdx.x;

    for (int i = tid; i < HEADS*DOTP; i += 256) {
        int h = i / DOTP, e = i - h*DOTP;
        float s = 0.f;
        for (int sp = 0; sp < NSPLIT; sp++)
            s += g_dotp[((size_t)sp*BATCH*HEADS + b*HEADS + h)*DOTP + e];
        buf[i] = s;
    }
    __syncthreads();

    if (tid < HEADS*CQH) {
        int h = tid / CQH, c = tid % CQH;
        const float* B = &buf[h*DOTP];
        float invq = 1.f / fmaxf(sqrtf(B[576 + c]), 1e-12f);
        float tah = ta[h];
        float l[CAH], m = -1e30f;
#pragma unroll
        for (int d = 0; d < CAH; d++) {
            float inva = 1.f / fmaxf(sqrtf(B[624 + d]), 1e-12f);
            l[d] = B[c*12 + d] * invq * inva * tah;
            m = fmaxf(m, l[d]);
        }
        float s = 0.f;
#pragma unroll
        for (int d = 0; d < CAH; d++) { l[d] = expf(l[d] - m); s += l[d]; }
        float inv = 1.f / s;
#pragma unroll
        for (int d = 0; d < CAH; d++) SA[h][c][d] = l[d] * inv;
    }
    if (tid < HEADS*CAH) {
        int h = tid / CAH, d = tid % CAH;
        const float* B = &buf[h*DOTP];
        float inva = 1.f / fmaxf(sqrtf(B[624 + d]), 1e-12f);
        float tvh = tv[h];
        float l[CQH], m = -1e30f;
#pragma unroll
        for (int c = 0; c < CQH; c++) {
            float invk = 1.f / fmaxf(sqrtf(B[600 + c]), 1e-12f);
            l[c] = B[288 + c*12 + d] * invk * inva * tvh;
            m = fmaxf(m, l[c]);
        }
        float s = 0.f;
#pragma unroll
        for (int c = 0; c < CQH; c++) { l[c] = expf(l[c] - m); s += l[c]; }
        float inv = 1.f / s;
#pragma unroll
        for (int c = 0; c < CQH; c++) SK[h][d][c] = l[c] * inv;
    }
    __syncthreads();

    float* M = buf;                           // 8*24*24 = 4608 <= 5120
    for (int i = tid; i < HEADS*CQH*CQH; i += 256) {
        int h = i / (CQH*CQH), r = (i / CQH) % CQH, j = i % CQH;
        float s = 0.f;
#pragma unroll
        for (int d = 0; d < CAH; d++) s = fmaf(SA[h][r][d], SK[h][d][j], s);
        M[(h*CQH + r)*CQH + j] = s;
    }
    __syncthreads();

    for (int i = tid; i < C*C; i += 256) {
        int cv = i / C, o = i % C;
        int hv = cv / CQH, j = cv % CQH;
        float s = 0.f;
#pragma unroll
        for (int k = 0; k < CQH; k++)
            s = fmaf(wo[o*C + hv*CQH + k], M[(hv*CQH + k)*CQH + j], s);
        g_weffT[(size_t)b*C*C + i] = s;       // [cv][o] layout
    }
}

// ---------------- tf32 GEMM: 64m x 128n tile, K=192 -------------------------
// MODE 0: g_v = (wv @ x) * illu;  MODE 1: out = W_eff @ g_v
template<int MODE>
__global__ __launch_bounds__(256) void tgemm_kernel(const float* __restrict__ xin,
                                                    const float* __restrict__ illu,
                                                    float* __restrict__ outp)
{
    __shared__ unsigned As[32][72];
    __shared__ unsigned Bs[32][136];
    int b = blockIdx.z, mt = blockIdx.y;
    int n0 = blockIdx.x * 128;
    int m0 = mt * 64;
    const float* A = (MODE == 0) ? g_wvT : (g_weffT + (size_t)b*C*C);
    const float* B = ((MODE == 0) ? xin : g_v) + (size_t)b*C*NPIXF;
    float*       O = ((MODE == 0) ? g_v : outp) + (size_t)b*C*NPIXF;
    const float* Ib = (MODE == 0) ? (illu + (size_t)b*C*NPIXF) : nullptr;

    int tid = threadIdx.x;
    int warp = tid >> 5, lane = tid & 31;
    int wm = warp >> 2, wn = warp & 3;
    int g = lane >> 2, tg = lane & 3;

    float acc[2][4][4];
#pragma unroll
    for (int a = 0; a < 2; a++)
#pragma unroll
        for (int bn = 0; bn < 4; bn++)
#pragma unroll
            for (int q = 0; q < 4; q++) acc[a][bn][q] = 0.f;

    for (int k0 = 0; k0 < C; k0 += 32) {
        __syncthreads();
        for (int i = tid; i < 512; i += 256) {
            int kk = i >> 4, m4 = (i & 15) * 4;
            float4 v4 = *(const float4*)&A[(k0+kk)*C + m0 + m4];
            *(uint4*)&As[kk][m4] = make_uint4(f2tf(v4.x), f2tf(v4.y), f2tf(v4.z), f2tf(v4.w));
        }
        for (int i = tid; i < 1024; i += 256) {
            int kk = i >> 5, n4 = (i & 31) * 4;
            float4 v4 = *(const float4*)&B[(size_t)(k0+kk)*NPIXF + n0 + n4];
            *(uint4*)&Bs[kk][n4] = make_uint4(f2tf(v4.x), f2tf(v4.y), f2tf(v4.z), f2tf(v4.w));
        }
        __syncthreads();
#pragma unroll
        for (int k8 = 0; k8 < 4; k8++) {
            int kb = k8 * 8;
            unsigned a[2][4], bb[4][2];
#pragma unroll
            for (int mf = 0; mf < 2; mf++) {
                int mb = wm*32 + mf*16 + g;
                a[mf][0] = As[kb+tg][mb];     a[mf][1] = As[kb+tg][mb+8];
                a[mf][2] = As[kb+tg+4][mb];   a[mf][3] = As[kb+tg+4][mb+8];
            }
#pragma unroll
            for (int nf = 0; nf < 4; nf++) {
                int nb = wn*32 + nf*8 + g;
                bb[nf][0] = Bs[kb+tg][nb];    bb[nf][1] = Bs[kb+tg+4][nb];
            }
#pragma unroll
            for (int mf = 0; mf < 2; mf++)
#pragma unroll
                for (int nf = 0; nf < 4; nf++)
                    mma_tf32(acc[mf][nf][0], acc[mf][nf][1], acc[mf][nf][2], acc[mf][nf][3],
                             a[mf][0], a[mf][1], a[mf][2], a[mf][3], bb[nf][0], bb[nf][1]);
        }
    }
#pragma unroll
    for (int mf = 0; mf < 2; mf++)
#pragma unroll
        for (int nf = 0; nf < 4; nf++) {
            int m = m0 + wm*32 + mf*16 + g;
            int n = n0 + wn*32 + nf*8 + tg*2;
            float2 v0 = make_float2(acc[mf][nf][0], acc[mf][nf][1]);
            float2 v1 = make_float2(acc[mf][nf][2], acc[mf][nf][3]);
            if (MODE == 0) {
                float2 i0 = *(const float2*)&Ib[(size_t)m*NPIXF + n];
                float2 i1 = *(const float2*)&Ib[(size_t)(m+8)*NPIXF + n];
                v0.x *= i0.x; v0.y *= i0.y;
                v1.x *= i1.x; v1.y *= i1.y;
            }
            *(float2*)&O[(size_t)m*NPIXF + n] = v0;
            *(float2*)&O[(size_t)(m+8)*NPIXF + n] = v1;
        }
}

// ---------------- launch ----------------------------------------------------
extern "C" void kernel_launch(void* const* d_in, const int* in_sizes, int n_in,
                              void* d_out, int out_size)
{
    const float* x    = (const float*)d_in[0];
    const float* illu = (const float*)d_in[1];
    const float* wq   = (const float*)d_in[2];
    const float* wk   = (const float*)d_in[3];
    const float* wadw = (const float*)d_in[4];
    const float* wapw = (const float*)d_in[5];
    const float* bapw = (const float*)d_in[6];
    const float* wv   = (const float*)d_in[7];
    const float* wo   = (const float*)d_in[8];
    const float* ta   = (const float*)d_in[9];
    const float* tv   = (const float*)d_in[10];
    float* out = (float*)d_out;

    prep_kernel   <<<1440, 256>>>(wk, wv);
    zeropad_kernel<<<BATCH*C*4, 288>>>();
    split_kernel  <<<dim3(256, BATCH*C), 256>>>(x);
    dw_kernel     <<<dim3(NPIX/256, BATCH*C), 256>>>(x, wq, wadw);
    kconv_kernel  <<<dim3(128, 3, BATCH), 256>>>();
    apw_kernel    <<<dim3(NPIX/64, BATCH), 256>>>(wapw, bapw);
    tgemm_kernel<0><<<dim3(NPIXF/128, 3, BATCH), 256>>>(x, illu, nullptr);
    attn_kernel   <<<dim3(NSPLIT, BATCH*HEADS), 768>>>();
    combine_kernel<<<BATCH, 256>>>(wo, ta, tv);
    tgemm_kernel<1><<<dim3(NPIXF/128, 3, BATCH), 256>>>(nullptr, nullptr, out);
}

// round 3
// speedup vs baseline: 2.6866x; 1.4619x over previous
#include <cuda_runtime.h>
#include <cstdint>

#define BATCH 4
#define C 192
#define HW 256
#define HO 128
#define NPIX (HO*HO)      // 16384
#define NPIXF (HW*HW)     // 65536
#define HEADS 8
#define CQH 24
#define CAH 12
#define CA 96
#define KKDIM (C*9)       // 1728
#define PLANE (129*132)
#define NSPLIT 8
#define DOTP 640

// ---------------- scratch ----------------
__device__ float    g_q[BATCH*C*NPIX];
__device__ float    g_k[BATCH*C*NPIX];
__device__ float    g_adw[BATCH*C*NPIX];
__device__ float    g_a[BATCH*CA*NPIX];
__device__ unsigned g_v[(size_t)BATCH*C*NPIXF];      // tf32 bits
__device__ unsigned g_xp[(size_t)BATCH*C*4*PLANE];   // tf32 bits
__device__ unsigned g_wkT[KKDIM*C];                  // tf32 bits
__device__ unsigned g_wvT[C*C];                      // tf32 bits
__device__ unsigned g_weffT[BATCH*C*C];              // tf32 bits
__device__ float    g_dotp[(size_t)NSPLIT*BATCH*HEADS*DOTP];

// ---------------- helpers ----------------
__device__ __forceinline__ unsigned f2tf(float f){
    unsigned r; asm("cvt.rna.tf32.f32 %0, %1;" : "=r"(r) : "f"(f)); return r;
}
__device__ __forceinline__ void mma_tf32(float& c0, float& c1, float& c2, float& c3,
                                         unsigned a0, unsigned a1, unsigned a2, unsigned a3,
                                         unsigned b0, unsigned b1){
    asm volatile("mma.sync.aligned.m16n8k8.row.col.f32.tf32.tf32.f32 "
                 "{%0,%1,%2,%3},{%4,%5,%6,%7},{%8,%9},{%0,%1,%2,%3};"
                 : "+f"(c0), "+f"(c1), "+f"(c2), "+f"(c3)
                 : "r"(a0), "r"(a1), "r"(a2), "r"(a3), "r"(b0), "r"(b1));
}
__device__ __forceinline__ void cpa16(void* s, const void* g){
    unsigned sa = (unsigned)__cvta_generic_to_shared(s);
    asm volatile("cp.async.ca.shared.global [%0],[%1],16;" :: "r"(sa), "l"(g));
}
__device__ __forceinline__ void cpa4(void* s, const void* g){
    unsigned sa = (unsigned)__cvta_generic_to_shared(s);
    asm volatile("cp.async.ca.shared.global [%0],[%1],4;" :: "r"(sa), "l"(g));
}
#define CP_COMMIT asm volatile("cp.async.commit_group;")

// ---------------- prep: wk -> [k][oc] tf32, wv -> [ic][oc] tf32 -------------
__global__ __launch_bounds__(256) void prep_kernel(const float* __restrict__ wk,
                                                   const float* __restrict__ wv)
{
    int i = blockIdx.x * 256 + threadIdx.x;
    if (i < KKDIM*C) {
        int k = i / C, oc = i % C;
        g_wkT[i] = f2tf(wk[oc*KKDIM + k]);
    } else {
        int j = i - KKDIM*C;
        if (j < C*C) {
            int ic = j / C, oc = j % C;
            g_wvT[j] = f2tf(wv[oc*C + ic]);
        }
    }
}

// ---------------- zero pad borders of phase planes --------------------------
__global__ void zeropad_kernel()
{
    size_t base = (size_t)blockIdx.x * PLANE;
    int t = threadIdx.x;
    if (t < 132) g_xp[base + t] = 0u;
    int r = t - 131;
    if (t >= 132 && r <= 128) g_xp[base + r*132] = 0u;
}

// ---------------- fused: parity-plane split + depthwise q/adw ---------------
__global__ __launch_bounds__(256) void sdq_kernel(const float* __restrict__ x,
                                                  const float* __restrict__ wq,
                                                  const float* __restrict__ wadw)
{
    __shared__ float xs[66][68];
    int bc = blockIdx.y;
    int c  = bc % C;
    int tile = blockIdx.x;              // 0..15
    int oy0 = (tile >> 2) * 32, ox0 = (tile & 3) * 32;
    int iy0 = 2*oy0 - 1, ix0 = 2*ox0 - 1;
    const float* xp = x + (size_t)bc * NPIXF;
    int tid = threadIdx.x;

    for (int i = tid; i < 66*66; i += 256) {
        int r = i / 66, cc = i - r*66;
        int iy = iy0 + r, ix = ix0 + cc;
        float v = 0.f;
        if (iy >= 0 && iy < HW && ix >= 0 && ix < HW) v = xp[iy*HW + ix];
        xs[r][cc] = v;
    }
    __syncthreads();

    // parity-plane writes (tf32 bits)
    size_t pbase = (size_t)bc * 4 * PLANE;
    for (int i = tid; i < 4096; i += 256) {
        int ly = i >> 6, lx = i & 63;
        int ph = ((ly & 1) << 1) | (lx & 1);
        g_xp[pbase + (size_t)ph*PLANE + (oy0 + (ly>>1) + 1)*132 + ox0 + (lx>>1) + 1]
            = f2tf(xs[ly + 1][lx + 1]);
    }

    // depthwise convs
    float wqr[9], war[9];
#pragma unroll
    for (int i = 0; i < 9; i++) { wqr[i] = wq[c*9+i]; war[i] = wadw[c*9+i]; }
#pragma unroll
    for (int j = 0; j < 4; j++) {
        int oyl = (tid >> 5) + j*8, oxl = tid & 31;
        float aq = 0.f, aa = 0.f;
#pragma unroll
        for (int ky = 0; ky < 3; ky++)
#pragma unroll
            for (int kx = 0; kx < 3; kx++) {
                float v = xs[2*oyl + ky][2*oxl + kx];
                aq = fmaf(wqr[ky*3+kx], v, aq);
                aa = fmaf(war[ky*3+kx], v, aa);
            }
        size_t o = (size_t)bc * NPIX + (oy0 + oyl)*HO + ox0 + oxl;
        g_q[o] = aq;
        g_adw[o] = aa;
    }
}

// ---------------- kconv: pipelined tf32 implicit GEMM, M=192 x N=128 --------
// dyn smem: As 2*32*200, Bs 2*32*136, rowoff 1728 (uint words)
#define KC_AS 6400
#define KC_BS 4352
__global__ __launch_bounds__(256) void kconv_kernel()
{
    extern __shared__ unsigned smm[];
    unsigned* Asm = smm;                     // 2*6400
    unsigned* Bsm = smm + 2*KC_AS;           // 2*4352
    int* rowoff = (int*)(smm + 2*KC_AS + 2*KC_BS);

    int b = blockIdx.y;
    int tile = blockIdx.x;                   // 0..127
    int oy0 = (tile >> 3) * 8, ox0 = (tile & 7) * 16;
    int tid = threadIdx.x;
    int warp = tid >> 5, lane = tid & 31;
    int wm = warp >> 1, wn = warp & 1;
    int g = lane >> 2, tg = lane & 3;

    for (int k = tid; k < KKDIM; k += 256) {
        int ic = k / 9, t = k - ic*9;
        int ky = t / 3, kx = t - ky*3;
        int py = (ky == 1) ? 0 : 1, px = (kx == 1) ? 0 : 1;
        int dy = (ky == 0) ? 0 : 1, dx = (kx == 0) ? 0 : 1;
        rowoff[k] = ((b*C + ic)*4 + py*2 + px)*PLANE + (oy0+dy)*132 + (ox0+dx);
    }
    __syncthreads();

    float acc[3][8][4];
#pragma unroll
    for (int mf = 0; mf < 3; mf++)
#pragma unroll
        for (int nf = 0; nf < 8; nf++)
#pragma unroll
            for (int q = 0; q < 4; q++) acc[mf][nf][q] = 0.f;

    // fill chunk 0 -> buf 0
    {
        for (int i = tid; i < 1536; i += 256) {
            int kk = i / 48, m4 = (i % 48) * 4;
            cpa16(&Asm[kk*200 + m4], &g_wkT[kk*C + m4]);
        }
        for (int i = tid; i < 4096; i += 256) {
            int kk = i >> 7, cc = i & 127;
            cpa4(&Bsm[kk*136 + cc], &g_xp[rowoff[kk] + (cc>>4)*132 + (cc&15)]);
        }
        CP_COMMIT;
    }

#pragma unroll 1
    for (int c2 = 0; c2 < 54; c2++) {
        int p = c2 & 1;
        if (c2 + 1 < 54) {
            int q2 = p ^ 1;
            int k0 = (c2 + 1) * 32;
            for (int i = tid; i < 1536; i += 256) {
                int kk = i / 48, m4 = (i % 48) * 4;
                cpa16(&Asm[q2*KC_AS + kk*200 + m4], &g_wkT[(k0+kk)*C + m4]);
            }
            for (int i = tid; i < 4096; i += 256) {
                int kk = i >> 7, cc = i & 127;
                cpa4(&Bsm[q2*KC_BS + kk*136 + cc],
                     &g_xp[rowoff[k0+kk] + (cc>>4)*132 + (cc&15)]);
            }
            CP_COMMIT;
            asm volatile("cp.async.wait_group 1;");
        } else {
            asm volatile("cp.async.wait_group 0;");
        }
        __syncthreads();

        const unsigned* Ab = &Asm[p*KC_AS];
        const unsigned* Bb = &Bsm[p*KC_BS];
#pragma unroll
        for (int k8 = 0; k8 < 4; k8++) {
            int kb = k8 * 8;
            unsigned a[3][4], bb[8][2];
#pragma unroll
            for (int mf = 0; mf < 3; mf++) {
                int mb = wm*48 + mf*16 + g;
                a[mf][0] = Ab[(kb+tg)*200 + mb];     a[mf][1] = Ab[(kb+tg)*200 + mb + 8];
                a[mf][2] = Ab[(kb+tg+4)*200 + mb];   a[mf][3] = Ab[(kb+tg+4)*200 + mb + 8];
            }
#pragma unroll
            for (int nf = 0; nf < 8; nf++) {
                int nb = wn*64 + nf*8 + g;
                bb[nf][0] = Bb[(kb+tg)*136 + nb];    bb[nf][1] = Bb[(kb+tg+4)*136 + nb];
            }
#pragma unroll
            for (int mf = 0; mf < 3; mf++)
#pragma unroll
                for (int nf = 0; nf < 8; nf++)
                    mma_tf32(acc[mf][nf][0], acc[mf][nf][1], acc[mf][nf][2], acc[mf][nf][3],
                             a[mf][0], a[mf][1], a[mf][2], a[mf][3], bb[nf][0], bb[nf][1]);
        }
        __syncthreads();
    }

#pragma unroll
    for (int mf = 0; mf < 3; mf++)
#pragma unroll
        for (int nf = 0; nf < 8; nf++) {
            int m = wm*48 + mf*16 + g;
            int n = wn*64 + nf*8 + tg*2;
            int oy = oy0 + (n >> 4), ox = ox0 + (n & 15);
            *(float2*)&g_k[(size_t)(b*C + m)*NPIX + oy*HO + ox] =
                make_float2(acc[mf][nf][0], acc[mf][nf][1]);
            *(float2*)&g_k[(size_t)(b*C + m + 8)*NPIX + oy*HO + ox] =
                make_float2(acc[mf][nf][2], acc[mf][nf][3]);
        }
}

// ---------------- pointwise 192->96 (+bias) on a_dw -------------------------
__global__ __launch_bounds__(256) void apw_kernel(const float* __restrict__ wapw,
                                                  const float* __restrict__ bapw)
{
    __shared__ float s[C*64];
    int b = blockIdx.y;
    int p0 = blockIdx.x * 64;
    for (int i = threadIdx.x; i < C*64; i += 256) {
        int cc = i >> 6, pp = i & 63;
        s[i] = g_adw[(size_t)(b*C + cc)*NPIX + p0 + pp];
    }
    __syncthreads();
    int pg  = threadIdx.x & 15;
    int ocb = threadIdx.x >> 4;
    for (int oc = ocb; oc < CA; oc += 16) {
        float bsv = bapw[oc];
        float4 acc = make_float4(bsv, bsv, bsv, bsv);
        for (int ic = 0; ic < C; ic++) {
            float w = __ldg(&wapw[oc*C + ic]);
            float4 xv = *reinterpret_cast<const float4*>(&s[ic*64 + pg*4]);
            acc.x = fmaf(w, xv.x, acc.x);
            acc.y = fmaf(w, xv.y, acc.y);
            acc.z = fmaf(w, xv.z, acc.z);
            acc.w = fmaf(w, xv.w, acc.w);
        }
        *reinterpret_cast<float4*>(&g_a[(size_t)(b*CA + oc)*NPIX + p0 + pg*4]) = acc;
    }
}

// ---------------- attention dots + fused norms ------------------------------
__global__ __launch_bounds__(768) void attn_kernel()
{
    __shared__ float a_s[CAH][256];
    int split = blockIdx.x, bh = blockIdx.y;
    int b = bh >> 3, h = bh & 7;
    int tid = threadIdx.x, warp = tid >> 5, lane = tid & 31;
    const float* qp = g_q + (size_t)(b*C + h*CQH + warp)*NPIX;
    const float* kp = g_k + (size_t)(b*C + h*CQH + warp)*NPIX;
    const float* ap = g_a + (size_t)(b*CA + h*CAH)*NPIX;
    int p0 = split * (NPIX / NSPLIT);

    float dq[12], dk[12];
#pragma unroll
    for (int d = 0; d < 12; d++) { dq[d] = 0.f; dk[d] = 0.f; }
    float qq = 0.f, kk = 0.f, aa = 0.f;

    for (int c0 = 0; c0 < NPIX/NSPLIT; c0 += 256) {
        for (int i = tid; i < CAH*256; i += 768) {
            int d = i >> 8, p = i & 255;
            a_s[d][p] = ap[(size_t)d*NPIX + p0 + c0 + p];
        }
        __syncthreads();
#pragma unroll
        for (int hf = 0; hf < 2; hf++) {
            int p = hf*128 + lane*4;
            float4 qv = *(const float4*)&qp[p0 + c0 + p];
            float4 kv = *(const float4*)&kp[p0 + c0 + p];
            qq += qv.x*qv.x + qv.y*qv.y + qv.z*qv.z + qv.w*qv.w;
            kk += kv.x*kv.x + kv.y*kv.y + kv.z*kv.z + kv.w*kv.w;
            if (warp < CAH) {
                float4 av = *(const float4*)&a_s[warp][p];
                aa += av.x*av.x + av.y*av.y + av.z*av.z + av.w*av.w;
            }
#pragma unroll
            for (int d = 0; d < 12; d++) {
                float4 av = *(const float4*)&a_s[d][p];
                dq[d] += qv.x*av.x + qv.y*av.y + qv.z*av.z + qv.w*av.w;
                dk[d] += kv.x*av.x + kv.y*av.y + kv.z*av.z + kv.w*av.w;
            }
        }
        __syncthreads();
    }
#pragma unroll
    for (int off = 16; off; off >>= 1) {
#pragma unroll
        for (int d = 0; d < 12; d++) {
            dq[d] += __shfl_down_sync(0xffffffffu, dq[d], off);
            dk[d] += __shfl_down_sync(0xffffffffu, dk[d], off);
        }
        qq += __shfl_down_sync(0xffffffffu, qq, off);
        kk += __shfl_down_sync(0xffffffffu, kk, off);
        aa += __shfl_down_sync(0xffffffffu, aa, off);
    }
    if (lane == 0) {
        float* out = &g_dotp[((size_t)split*BATCH*HEADS + bh)*DOTP];
#pragma unroll
        for (int d = 0; d < 12; d++) {
            out[warp*12 + d]       = dq[d];
            out[288 + warp*12 + d] = dk[d];
        }
        out[576 + warp] = qq;
        out[600 + warp] = kk;
        if (warp < 12) out[624 + warp] = aa;
    }
}

// ---------------- combine: norms, softmax, M, W_eff^T (tf32) ----------------
__global__ __launch_bounds__(256) void combine_kernel(const float* __restrict__ wo,
                                                      const float* __restrict__ ta,
                                                      const float* __restrict__ tv)
{
    __shared__ float buf[HEADS*DOTP];
    __shared__ float SA[HEADS][CQH][CAH];
    __shared__ float SK[HEADS][CAH][CQH];
    int b = blockIdx.x, tid = threadIdx.x;

    for (int i = tid; i < HEADS*DOTP; i += 256) {
        int h = i / DOTP, e = i - h*DOTP;
        float s = 0.f;
        for (int sp = 0; sp < NSPLIT; sp++)
            s += g_dotp[((size_t)sp*BATCH*HEADS + b*HEADS + h)*DOTP + e];
        buf[i] = s;
    }
    __syncthreads();

    if (tid < HEADS*CQH) {
        int h = tid / CQH, c = tid % CQH;
        const float* B = &buf[h*DOTP];
        float invq = 1.f / fmaxf(sqrtf(B[576 + c]), 1e-12f);
        float tah = ta[h];
        float l[CAH], m = -1e30f;
#pragma unroll
        for (int d = 0; d < CAH; d++) {
            float inva = 1.f / fmaxf(sqrtf(B[624 + d]), 1e-12f);
            l[d] = B[c*12 + d] * invq * inva * tah;
            m = fmaxf(m, l[d]);
        }
        float s = 0.f;
#pragma unroll
        for (int d = 0; d < CAH; d++) { l[d] = expf(l[d] - m); s += l[d]; }
        float inv = 1.f / s;
#pragma unroll
        for (int d = 0; d < CAH; d++) SA[h][c][d] = l[d] * inv;
    }
    if (tid < HEADS*CAH) {
        int h = tid / CAH, d = tid % CAH;
        const float* B = &buf[h*DOTP];
        float inva = 1.f / fmaxf(sqrtf(B[624 + d]), 1e-12f);
        float tvh = tv[h];
        float l[CQH], m = -1e30f;
#pragma unroll
        for (int c = 0; c < CQH; c++) {
            float invk = 1.f / fmaxf(sqrtf(B[600 + c]), 1e-12f);
            l[c] = B[288 + c*12 + d] * invk * inva * tvh;
            m = fmaxf(m, l[c]);
        }
        float s = 0.f;
#pragma unroll
        for (int c = 0; c < CQH; c++) { l[c] = expf(l[c] - m); s += l[c]; }
        float inv = 1.f / s;
#pragma unroll
        for (int c = 0; c < CQH; c++) SK[h][d][c] = l[c] * inv;
    }
    __syncthreads();

    float* M = buf;
    for (int i = tid; i < HEADS*CQH*CQH; i += 256) {
        int h = i / (CQH*CQH), r = (i / CQH) % CQH, j = i % CQH;
        float s = 0.f;
#pragma unroll
        for (int d = 0; d < CAH; d++) s = fmaf(SA[h][r][d], SK[h][d][j], s);
        M[(h*CQH + r)*CQH + j] = s;
    }
    __syncthreads();

    for (int i = tid; i < C*C; i += 256) {
        int cv = i / C, o = i % C;
        int hv = cv / CQH, j = cv % CQH;
        float s = 0.f;
#pragma unroll
        for (int k = 0; k < CQH; k++)
            s = fmaf(wo[o*C + hv*CQH + k], M[(hv*CQH + k)*CQH + j], s);
        g_weffT[(size_t)b*C*C + i] = f2tf(s);
    }
}

// ---------------- pipelined tf32 GEMM: M=192 x N=128, K=192 -----------------
// MODE 0: g_v = tf32((wv @ x) * illu);  MODE 1: out = W_eff @ v
template<int MODE>
__global__ __launch_bounds__(256) void tgemm_kernel(const float* __restrict__ xin,
                                                    const float* __restrict__ illu,
                                                    float* __restrict__ outp)
{
    extern __shared__ unsigned smm[];
    unsigned* Asm = smm;                     // 2*6400
    unsigned* Bsm = smm + 2*KC_AS;           // 2*4352

    int b = blockIdx.z;
    int n0 = blockIdx.x * 128;
    const unsigned* A = (MODE == 0) ? g_wvT : (g_weffT + (size_t)b*C*C);
    const float* Bf = (MODE == 0) ? (xin + (size_t)b*C*NPIXF) : nullptr;
    const unsigned* Bu = (MODE == 1) ? (g_v + (size_t)b*C*NPIXF) : nullptr;
    const float* Ib = (MODE == 0) ? (illu + (size_t)b*C*NPIXF) : nullptr;

    int tid = threadIdx.x;
    int warp = tid >> 5, lane = tid & 31;
    int wm = warp >> 1, wn = warp & 1;
    int g = lane >> 2, tg = lane & 3;

    float acc[3][8][4];
#pragma unroll
    for (int mf = 0; mf < 3; mf++)
#pragma unroll
        for (int nf = 0; nf < 8; nf++)
#pragma unroll
            for (int q = 0; q < 4; q++) acc[mf][nf][q] = 0.f;

    // prologue: chunk 0 -> buf 0
    for (int i = tid; i < 1536; i += 256) {
        int kk = i / 48, m4 = (i % 48) * 4;
        cpa16(&Asm[kk*200 + m4], &A[kk*C + m4]);
    }
    if (MODE == 1) {
        for (int j = 0; j < 4; j++) {
            int i = tid + j*256;
            int kk = i >> 5, n4 = (i & 31) * 4;
            cpa16(&Bsm[kk*136 + n4], &Bu[(size_t)kk*NPIXF + n0 + n4]);
        }
    }
    CP_COMMIT;
    if (MODE == 0) {
        float4 tmp[4];
#pragma unroll
        for (int j = 0; j < 4; j++) {
            int i = tid + j*256;
            int kk = i >> 5, n4 = (i & 31) * 4;
            tmp[j] = *(const float4*)&Bf[(size_t)kk*NPIXF + n0 + n4];
        }
#pragma unroll
        for (int j = 0; j < 4; j++) {
            int i = tid + j*256;
            int kk = i >> 5, n4 = (i & 31) * 4;
            *(uint4*)&Bsm[kk*136 + n4] =
                make_uint4(f2tf(tmp[j].x), f2tf(tmp[j].y), f2tf(tmp[j].z), f2tf(tmp[j].w));
        }
    }

    float4 tmp[4];
#pragma unroll 1
    for (int c2 = 0; c2 < 6; c2++) {
        int p = c2 & 1;
        int q2 = p ^ 1;
        if (c2 + 1 < 6) {
            int k0 = (c2 + 1) * 32;
            for (int i = tid; i < 1536; i += 256) {
                int kk = i / 48, m4 = (i % 48) * 4;
                cpa16(&Asm[q2*KC_AS + kk*200 + m4], &A[(k0+kk)*C + m4]);
            }
            if (MODE == 1) {
#pragma unroll
                for (int j = 0; j < 4; j++) {
                    int i = tid + j*256;
                    int kk = i >> 5, n4 = (i & 31) * 4;
                    cpa16(&Bsm[q2*KC_BS + kk*136 + n4],
                          &Bu[(size_t)(k0+kk)*NPIXF + n0 + n4]);
                }
            }
            CP_COMMIT;
            if (MODE == 0) {
#pragma unroll
                for (int j = 0; j < 4; j++) {
                    int i = tid + j*256;
                    int kk = i >> 5, n4 = (i & 31) * 4;
                    tmp[j] = *(const float4*)&Bf[(size_t)(k0+kk)*NPIXF + n0 + n4];
                }
            }
            asm volatile("cp.async.wait_group 1;");
        } else {
            asm volatile("cp.async.wait_group 0;");
        }
        __syncthreads();

        const unsigned* Ab = &Asm[p*KC_AS];
        const unsigned* Bb = &Bsm[p*KC_BS];
#pragma unroll
        for (int k8 = 0; k8 < 4; k8++) {
            int kb = k8 * 8;
            unsigned a[3][4], bb[8][2];
#pragma unroll
            for (int mf = 0; mf < 3; mf++) {
                int mb = wm*48 + mf*16 + g;
                a[mf][0] = Ab[(kb+tg)*200 + mb];     a[mf][1] = Ab[(kb+tg)*200 + mb + 8];
                a[mf][2] = Ab[(kb+tg+4)*200 + mb];   a[mf][3] = Ab[(kb+tg+4)*200 + mb + 8];
            }
#pragma unroll
            for (int nf = 0; nf < 8; nf++) {
                int nb = wn*64 + nf*8 + g;
                bb[nf][0] = Bb[(kb+tg)*136 + nb];    bb[nf][1] = Bb[(kb+tg+4)*136 + nb];
            }
#pragma unroll
            for (int mf = 0; mf < 3; mf++)
#pragma unroll
                for (int nf = 0; nf < 8; nf++)
                    mma_tf32(acc[mf][nf][0], acc[mf][nf][1], acc[mf][nf][2], acc[mf][nf][3],
                             a[mf][0], a[mf][1], a[mf][2], a[mf][3], bb[nf][0], bb[nf][1]);
        }
        if (MODE == 0 && c2 + 1 < 6) {
#pragma unroll
            for (int j = 0; j < 4; j++) {
                int i = tid + j*256;
                int kk = i >> 5, n4 = (i & 31) * 4;
                *(uint4*)&Bsm[q2*KC_BS + kk*136 + n4] =
                    make_uint4(f2tf(tmp[j].x), f2tf(tmp[j].y), f2tf(tmp[j].z), f2tf(tmp[j].w));
            }
        }
        __syncthreads();
    }

#pragma unroll
    for (int mf = 0; mf < 3; mf++)
#pragma unroll
        for (int nf = 0; nf < 8; nf++) {
            int m = wm*48 + mf*16 + g;
            int n = n0 + wn*64 + nf*8 + tg*2;
            if (MODE == 0) {
                float2 i0 = *(const float2*)&Ib[(size_t)m*NPIXF + n];
                float2 i1 = *(const float2*)&Ib[(size_t)(m+8)*NPIXF + n];
                unsigned* O = g_v + (size_t)b*C*NPIXF;
                *(uint2*)&O[(size_t)m*NPIXF + n] =
                    make_uint2(f2tf(acc[mf][nf][0]*i0.x), f2tf(acc[mf][nf][1]*i0.y));
                *(uint2*)&O[(size_t)(m+8)*NPIXF + n] =
                    make_uint2(f2tf(acc[mf][nf][2]*i1.x), f2tf(acc[mf][nf][3]*i1.y));
            } else {
                float* O = outp + (size_t)b*C*NPIXF;
                *(float2*)&O[(size_t)m*NPIXF + n] =
                    make_float2(acc[mf][nf][0], acc[mf][nf][1]);
                *(float2*)&O[(size_t)(m+8)*NPIXF + n] =
                    make_float2(acc[mf][nf][2], acc[mf][nf][3]);
            }
        }
}

// ---------------- launch ----------------------------------------------------
extern "C" void kernel_launch(void* const* d_in, const int* in_sizes, int n_in,
                              void* d_out, int out_size)
{
    const float* x    = (const float*)d_in[0];
    const float* illu = (const float*)d_in[1];
    const float* wq   = (const float*)d_in[2];
    const float* wk   = (const float*)d_in[3];
    const float* wadw = (const float*)d_in[4];
    const float* wapw = (const float*)d_in[5];
    const float* bapw = (const float*)d_in[6];
    const float* wv   = (const float*)d_in[7];
    const float* wo   = (const float*)d_in[8];
    const float* ta   = (const float*)d_in[9];
    const float* tv   = (const float*)d_in[10];
    float* out = (float*)d_out;

    const int kconv_smem = (2*KC_AS + 2*KC_BS + KKDIM) * 4;   // 92928
    const int tgemm_smem = (2*KC_AS + 2*KC_BS) * 4;           // 86016
    cudaFuncSetAttribute(kconv_kernel, cudaFuncAttributeMaxDynamicSharedMemorySize, kconv_smem);
    cudaFuncSetAttribute(tgemm_kernel<0>, cudaFuncAttributeMaxDynamicSharedMemorySize, tgemm_smem);
    cudaFuncSetAttribute(tgemm_kernel<1>, cudaFuncAttributeMaxDynamicSharedMemorySize, tgemm_smem);

    prep_kernel   <<<1440, 256>>>(wk, wv);
    zeropad_kernel<<<BATCH*C*4, 288>>>();
    sdq_kernel    <<<dim3(16, BATCH*C), 256>>>(x, wq, wadw);
    kconv_kernel  <<<dim3(128, BATCH), 256, kconv_smem>>>();
    apw_kernel    <<<dim3(NPIX/64, BATCH), 256>>>(wapw, bapw);
    tgemm_kernel<0><<<dim3(NPIXF/128, 1, BATCH), 256, tgemm_smem>>>(x, illu, nullptr);
    attn_kernel   <<<dim3(NSPLIT, BATCH*HEADS), 768>>>();
    combine_kernel<<<BATCH, 256>>>(wo, ta, tv);
    tgemm_kernel<1><<<dim3(NPIXF/128, 1, BATCH), 256, tgemm_smem>>>(nullptr, nullptr, out);
}

// round 6
// speedup vs baseline: 2.6893x; 1.0010x over previous
#include <cuda_runtime.h>
#include <cstdint>

#define BATCH 4
#define C 192
#define HW 256
#define HO 128
#define NPIX (HO*HO)      // 16384
#define NPIXF (HW*HW)     // 65536
#define HEADS 8
#define CQH 24
#define CAH 12
#define CA 96
#define KKDIM (C*9)       // 1728
#define PLANE (129*132)
#define NSPLIT 8
#define DOTP 640
#define KC_AS 6400
#define KC_BS 4352

// ---------------- scratch ----------------
__device__ float    g_q[BATCH*C*NPIX];
__device__ float    g_k[BATCH*C*NPIX];
__device__ float    g_adw[BATCH*C*NPIX];
__device__ float    g_a[BATCH*CA*NPIX];
__device__ unsigned g_v[(size_t)BATCH*C*NPIXF];      // tf32 bits
__device__ unsigned g_xp[(size_t)BATCH*C*4*PLANE];   // tf32 bits
__device__ unsigned g_wkT[KKDIM*C];                  // tf32 bits
__device__ unsigned g_wvT[C*C];                      // tf32 bits
__device__ unsigned g_weffT[BATCH*C*C];              // tf32 bits
__device__ float    g_dotp[(size_t)NSPLIT*BATCH*HEADS*DOTP];

// ---------------- helpers ----------------
__device__ __forceinline__ unsigned f2tf(float f){
    unsigned r; asm("cvt.rna.tf32.f32 %0, %1;" : "=r"(r) : "f"(f)); return r;
}
__device__ __forceinline__ void mma_tf32(float& c0, float& c1, float& c2, float& c3,
                                         unsigned a0, unsigned a1, unsigned a2, unsigned a3,
                                         unsigned b0, unsigned b1){
    asm volatile("mma.sync.aligned.m16n8k8.row.col.f32.tf32.tf32.f32 "
                 "{%0,%1,%2,%3},{%4,%5,%6,%7},{%8,%9},{%0,%1,%2,%3};"
                 : "+f"(c0), "+f"(c1), "+f"(c2), "+f"(c3)
                 : "r"(a0), "r"(a1), "r"(a2), "r"(a3), "r"(b0), "r"(b1));
}
__device__ __forceinline__ void cpa16(void* s, const void* g){
    unsigned sa = (unsigned)__cvta_generic_to_shared(s);
    asm volatile("cp.async.ca.shared.global [%0],[%1],16;" :: "r"(sa), "l"(g));
}
__device__ __forceinline__ void cpa4(void* s, const void* g){
    unsigned sa = (unsigned)__cvta_generic_to_shared(s);
    asm volatile("cp.async.ca.shared.global [%0],[%1],4;" :: "r"(sa), "l"(g));
}
#define CP_COMMIT asm volatile("cp.async.commit_group;")

// ================= preproc: prep + zeropad + sdq (fused launch) =============
__device__ void prep_body(int bid, const float* __restrict__ wk,
                          const float* __restrict__ wv)
{
    int i = bid * 256 + threadIdx.x;
    if (i < KKDIM*C) {
        int k = i / C, oc = i % C;
        g_wkT[i] = f2tf(wk[oc*KKDIM + k]);
    } else {
        int j = i - KKDIM*C;
        if (j < C*C) {
            int ic = j / C, oc = j % C;
            g_wvT[j] = f2tf(wv[oc*C + ic]);
        }
    }
}

__device__ void zeropad_body(int bid)
{
    size_t base = (size_t)bid * PLANE;
    for (int i = threadIdx.x; i < 260; i += 256) {
        if (i < 132) g_xp[base + i] = 0u;
        else         g_xp[base + (i - 131)*132] = 0u;
    }
}

__device__ void sdq_body(int bid, const float* __restrict__ x,
                         const float* __restrict__ wq,
                         const float* __restrict__ wadw)
{
    __shared__ float xs[66][68];
    int tile = bid & 15;
    int bc   = bid >> 4;
    int c    = bc % C;
    int oy0 = (tile >> 2) * 32, ox0 = (tile & 3) * 32;
    int iy0 = 2*oy0 - 1, ix0 = 2*ox0 - 1;
    const float* xp = x + (size_t)bc * NPIXF;
    int tid = threadIdx.x;

    for (int i = tid; i < 66*66; i += 256) {
        int r = i / 66, cc = i - r*66;
        int iy = iy0 + r, ix = ix0 + cc;
        float v = 0.f;
        if (iy >= 0 && iy < HW && ix >= 0 && ix < HW) v = xp[iy*HW + ix];
        xs[r][cc] = v;
    }
    __syncthreads();

    size_t pbase = (size_t)bc * 4 * PLANE;
    for (int i = tid; i < 4096; i += 256) {
        int ly = i >> 6, lx = i & 63;
        int ph = ((ly & 1) << 1) | (lx & 1);
        g_xp[pbase + (size_t)ph*PLANE + (oy0 + (ly>>1) + 1)*132 + ox0 + (lx>>1) + 1]
            = f2tf(xs[ly + 1][lx + 1]);
    }

    float wqr[9], war[9];
#pragma unroll
    for (int i = 0; i < 9; i++) { wqr[i] = wq[c*9+i]; war[i] = wadw[c*9+i]; }
#pragma unroll
    for (int j = 0; j < 4; j++) {
        int oyl = (tid >> 5) + j*8, oxl = tid & 31;
        float aq = 0.f, aa = 0.f;
#pragma unroll
        for (int ky = 0; ky < 3; ky++)
#pragma unroll
            for (int kx = 0; kx < 3; kx++) {
                float v = xs[2*oyl + ky][2*oxl + kx];
                aq = fmaf(wqr[ky*3+kx], v, aq);
                aa = fmaf(war[ky*3+kx], v, aa);
            }
        size_t o = (size_t)bc * NPIX + (oy0 + oyl)*HO + ox0 + oxl;
        g_q[o] = aq;
        g_adw[o] = aa;
    }
}

#define PREP_N 1440
#define ZP_N   (BATCH*C*4)
#define SDQ_N  (16*BATCH*C)
__global__ __launch_bounds__(256) void preproc_kernel(const float* __restrict__ x,
                                                      const float* __restrict__ wq,
                                                      const float* __restrict__ wadw,
                                                      const float* __restrict__ wk,
                                                      const float* __restrict__ wv)
{
    int bid = blockIdx.x;
    if (bid < SDQ_N)               sdq_body(bid, x, wq, wadw);
    else if (bid < SDQ_N + ZP_N)   zeropad_body(bid - SDQ_N);
    else                           prep_body(bid - SDQ_N - ZP_N, wk, wv);
}

// ================= kconv body: pipelined tf32 implicit GEMM =================
// B fill: cp.async.16 when the tap row is 16B aligned (kx==0), else 4x cp.async.4
__device__ __forceinline__ void kconv_fillB(unsigned* dstBase, const int* rowoff,
                                            int k0, int tid)
{
    for (int i = tid; i < 1024; i += 256) {
        int kk = i >> 5, g4 = i & 31;
        int pr = g4 >> 2, pc = (g4 & 3) * 4;
        int ro = rowoff[k0 + kk];
        const unsigned* gp = &g_xp[ro + pr*132 + pc];
        unsigned* sp = &dstBase[kk*136 + pr*16 + pc];
        if ((ro & 3) == 0) {
            cpa16(sp, gp);
        } else {
            cpa4(sp,     gp);
            cpa4(sp + 1, gp + 1);
            cpa4(sp + 2, gp + 2);
            cpa4(sp + 3, gp + 3);
        }
    }
}

__device__ void kconv_body(int bid)
{
    extern __shared__ unsigned smm[];
    unsigned* Asm = smm;
    unsigned* Bsm = smm + 2*KC_AS;
    int* rowoff = (int*)(smm + 2*KC_AS + 2*KC_BS);

    int b = bid >> 7;
    int tile = bid & 127;
    int oy0 = (tile >> 3) * 8, ox0 = (tile & 7) * 16;
    int tid = threadIdx.x;
    int warp = tid >> 5, lane = tid & 31;
    int wm = warp >> 1, wn = warp & 1;
    int g = lane >> 2, tg = lane & 3;

    for (int k = tid; k < KKDIM; k += 256) {
        int ic = k / 9, t = k - ic*9;
        int ky = t / 3, kx = t - ky*3;
        int py = (ky == 1) ? 0 : 1, px = (kx == 1) ? 0 : 1;
        int dy = (ky == 0) ? 0 : 1, dx = (kx == 0) ? 0 : 1;
        rowoff[k] = ((b*C + ic)*4 + py*2 + px)*PLANE + (oy0+dy)*132 + (ox0+dx);
    }
    __syncthreads();

    float acc[3][8][4];
#pragma unroll
    for (int mf = 0; mf < 3; mf++)
#pragma unroll
        for (int nf = 0; nf < 8; nf++)
#pragma unroll
            for (int q = 0; q < 4; q++) acc[mf][nf][q] = 0.f;

    // fill chunk 0 -> buf 0
    for (int i = tid; i < 1536; i += 256) {
        int kk = i / 48, m4 = (i % 48) * 4;
        cpa16(&Asm[kk*200 + m4], &g_wkT[kk*C + m4]);
    }
    kconv_fillB(Bsm, rowoff, 0, tid);
    CP_COMMIT;

#pragma unroll 1
    for (int c2 = 0; c2 < 54; c2++) {
        int p = c2 & 1;
        if (c2 + 1 < 54) {
            int q2 = p ^ 1;
            int k0 = (c2 + 1) * 32;
            for (int i = tid; i < 1536; i += 256) {
                int kk = i / 48, m4 = (i % 48) * 4;
                cpa16(&Asm[q2*KC_AS + kk*200 + m4], &g_wkT[(k0+kk)*C + m4]);
            }
            kconv_fillB(&Bsm[q2*KC_BS], rowoff, k0, tid);
            CP_COMMIT;
            asm volatile("cp.async.wait_group 1;");
        } else {
            asm volatile("cp.async.wait_group 0;");
        }
        __syncthreads();

        const unsigned* Ab = &Asm[p*KC_AS];
        const unsigned* Bb = &Bsm[p*KC_BS];
#pragma unroll
        for (int k8 = 0; k8 < 4; k8++) {
            int kb = k8 * 8;
            unsigned a[3][4], bb[8][2];
#pragma unroll
            for (int mf = 0; mf < 3; mf++) {
                int mb = wm*48 + mf*16 + g;
                a[mf][0] = Ab[(kb+tg)*200 + mb];     a[mf][1] = Ab[(kb+tg)*200 + mb + 8];
                a[mf][2] = Ab[(kb+tg+4)*200 + mb];   a[mf][3] = Ab[(kb+tg+4)*200 + mb + 8];
            }
#pragma unroll
            for (int nf = 0; nf < 8; nf++) {
                int nb = wn*64 + nf*8 + g;
                bb[nf][0] = Bb[(kb+tg)*136 + nb];    bb[nf][1] = Bb[(kb+tg+4)*136 + nb];
            }
#pragma unroll
            for (int mf = 0; mf < 3; mf++)
#pragma unroll
                for (int nf = 0; nf < 8; nf++)
                    mma_tf32(acc[mf][nf][0], acc[mf][nf][1], acc[mf][nf][2], acc[mf][nf][3],
                             a[mf][0], a[mf][1], a[mf][2], a[mf][3], bb[nf][0], bb[nf][1]);
        }
        __syncthreads();
    }

#pragma unroll
    for (int mf = 0; mf < 3; mf++)
#pragma unroll
        for (int nf = 0; nf < 8; nf++) {
            int m = wm*48 + mf*16 + g;
            int n = wn*64 + nf*8 + tg*2;
            int oy = oy0 + (n >> 4), ox = ox0 + (n & 15);
            *(float2*)&g_k[(size_t)(b*C + m)*NPIX + oy*HO + ox] =
                make_float2(acc[mf][nf][0], acc[mf][nf][1]);
            *(float2*)&g_k[(size_t)(b*C + m + 8)*NPIX + oy*HO + ox] =
                make_float2(acc[mf][nf][2], acc[mf][nf][3]);
        }
}

// ================= tgemm body: M=192 x N=128, K=192 =========================
template<int MODE>
__device__ void tgemm_body(int bid, const float* __restrict__ xin,
                           const float* __restrict__ illu,
                           float* __restrict__ outp)
{
    extern __shared__ unsigned smm[];
    unsigned* Asm = smm;
    unsigned* Bsm = smm + 2*KC_AS;

    int b = bid >> 9;
    int n0 = (bid & 511) * 128;
    const unsigned* A = (MODE == 0) ? g_wvT : (g_weffT + (size_t)b*C*C);
    const float* Bf = (MODE == 0) ? (xin + (size_t)b*C*NPIXF) : nullptr;
    const unsigned* Bu = (MODE == 1) ? (g_v + (size_t)b*C*NPIXF) : nullptr;
    const float* Ib = (MODE == 0) ? (illu + (size_t)b*C*NPIXF) : nullptr;

    int tid = threadIdx.x;
    int warp = tid >> 5, lane = tid & 31;
    int wm = warp >> 1, wn = warp & 1;
    int g = lane >> 2, tg = lane & 3;

    float acc[3][8][4];
#pragma unroll
    for (int mf = 0; mf < 3; mf++)
#pragma unroll
        for (int nf = 0; nf < 8; nf++)
#pragma unroll
            for (int q = 0; q < 4; q++) acc[mf][nf][q] = 0.f;

    for (int i = tid; i < 1536; i += 256) {
        int kk = i / 48, m4 = (i % 48) * 4;
        cpa16(&Asm[kk*200 + m4], &A[kk*C + m4]);
    }
    if (MODE == 1) {
        for (int j = 0; j < 4; j++) {
            int i = tid + j*256;
            int kk = i >> 5, n4 = (i & 31) * 4;
            cpa16(&Bsm[kk*136 + n4], &Bu[(size_t)kk*NPIXF + n0 + n4]);
        }
    }
    CP_COMMIT;
    if (MODE == 0) {
        float4 t0[4];
#pragma unroll
        for (int j = 0; j < 4; j++) {
            int i = tid + j*256;
            int kk = i >> 5, n4 = (i & 31) * 4;
            t0[j] = *(const float4*)&Bf[(size_t)kk*NPIXF + n0 + n4];
        }
#pragma unroll
        for (int j = 0; j < 4; j++) {
            int i = tid + j*256;
            int kk = i >> 5, n4 = (i & 31) * 4;
            *(uint4*)&Bsm[kk*136 + n4] =
                make_uint4(f2tf(t0[j].x), f2tf(t0[j].y), f2tf(t0[j].z), f2tf(t0[j].w));
        }
    }

    float4 tmp[4];
#pragma unroll 1
    for (int c2 = 0; c2 < 6; c2++) {
        int p = c2 & 1;
        int q2 = p ^ 1;
        if (c2 + 1 < 6) {
            int k0 = (c2 + 1) * 32;
            for (int i = tid; i < 1536; i += 256) {
                int kk = i / 48, m4 = (i % 48) * 4;
                cpa16(&Asm[q2*KC_AS + kk*200 + m4], &A[(k0+kk)*C + m4]);
            }
            if (MODE == 1) {
#pragma unroll
                for (int j = 0; j < 4; j++) {
                    int i = tid + j*256;
                    int kk = i >> 5, n4 = (i & 31) * 4;
                    cpa16(&Bsm[q2*KC_BS + kk*136 + n4],
                          &Bu[(size_t)(k0+kk)*NPIXF + n0 + n4]);
                }
            }
            CP_COMMIT;
            if (MODE == 0) {
#pragma unroll
                for (int j = 0; j < 4; j++) {
                    int i = tid + j*256;
                    int kk = i >> 5, n4 = (i & 31) * 4;
                    tmp[j] = *(const float4*)&Bf[(size_t)(k0+kk)*NPIXF + n0 + n4];
                }
            }
            asm volatile("cp.async.wait_group 1;");
        } else {
            asm volatile("cp.async.wait_group 0;");
        }
        __syncthreads();

        const unsigned* Ab = &Asm[p*KC_AS];
        const unsigned* Bb = &Bsm[p*KC_BS];
#pragma unroll
        for (int k8 = 0; k8 < 4; k8++) {
            int kb = k8 * 8;
            unsigned a[3][4], bb[8][2];
#pragma unroll
            for (int mf = 0; mf < 3; mf++) {
                int mb = wm*48 + mf*16 + g;
                a[mf][0] = Ab[(kb+tg)*200 + mb];     a[mf][1] = Ab[(kb+tg)*200 + mb + 8];
                a[mf][2] = Ab[(kb+tg+4)*200 + mb];   a[mf][3] = Ab[(kb+tg+4)*200 + mb + 8];
            }
#pragma unroll
            for (int nf = 0; nf < 8; nf++) {
                int nb = wn*64 + nf*8 + g;
                bb[nf][0] = Bb[(kb+tg)*136 + nb];    bb[nf][1] = Bb[(kb+tg+4)*136 + nb];
            }
#pragma unroll
            for (int mf = 0; mf < 3; mf++)
#pragma unroll
                for (int nf = 0; nf < 8; nf++)
                    mma_tf32(acc[mf][nf][0], acc[mf][nf][1], acc[mf][nf][2], acc[mf][nf][3],
                             a[mf][0], a[mf][1], a[mf][2], a[mf][3], bb[nf][0], bb[nf][1]);
        }
        if (MODE == 0 && c2 + 1 < 6) {
#pragma unroll
            for (int j = 0; j < 4; j++) {
                int i = tid + j*256;
                int kk = i >> 5, n4 = (i & 31) * 4;
                *(uint4*)&Bsm[q2*KC_BS + kk*136 + n4] =
                    make_uint4(f2tf(tmp[j].x), f2tf(tmp[j].y), f2tf(tmp[j].z), f2tf(tmp[j].w));
            }
        }
        __syncthreads();
    }

#pragma unroll
    for (int mf = 0; mf < 3; mf++)
#pragma unroll
        for (int nf = 0; nf < 8; nf++) {
            int m = wm*48 + mf*16 + g;
            int n = n0 + wn*64 + nf*8 + tg*2;
            if (MODE == 0) {
                float2 i0 = *(const float2*)&Ib[(size_t)m*NPIXF + n];
                float2 i1 = *(const float2*)&Ib[(size_t)(m+8)*NPIXF + n];
                unsigned* O = g_v + (size_t)b*C*NPIXF;
                *(uint2*)&O[(size_t)m*NPIXF + n] =
                    make_uint2(f2tf(acc[mf][nf][0]*i0.x), f2tf(acc[mf][nf][1]*i0.y));
                *(uint2*)&O[(size_t)(m+8)*NPIXF + n] =
                    make_uint2(f2tf(acc[mf][nf][2]*i1.x), f2tf(acc[mf][nf][3]*i1.y));
            } else {
                float* O = outp + (size_t)b*C*NPIXF;
                *(float2*)&O[(size_t)m*NPIXF + n] =
                    make_float2(acc[mf][nf][0], acc[mf][nf][1]);
                *(float2*)&O[(size_t)(m+8)*NPIXF + n] =
                    make_float2(acc[mf][nf][2], acc[mf][nf][3]);
            }
        }
}

// ================= apw body: pointwise 192->96 (+bias) ======================
__device__ void apw_body(int bid, const float* __restrict__ wapw,
                         const float* __restrict__ bapw)
{
    extern __shared__ unsigned smm[];
    float* s = (float*)smm;               // C*64 floats = 48KB
    int b = bid >> 8;
    int p0 = (bid & 255) * 64;
    for (int i = threadIdx.x; i < C*64; i += 256) {
        int cc = i >> 6, pp = i & 63;
        s[i] = g_adw[(size_t)(b*C + cc)*NPIX + p0 + pp];
    }
    __syncthreads();
    int pg  = threadIdx.x & 15;
    int ocb = threadIdx.x >> 4;
    for (int oc = ocb; oc < CA; oc += 16) {
        float bsv = bapw[oc];
        float4 acc = make_float4(bsv, bsv, bsv, bsv);
        for (int ic = 0; ic < C; ic++) {
            float w = __ldg(&wapw[oc*C + ic]);
            float4 xv = *reinterpret_cast<const float4*>(&s[ic*64 + pg*4]);
            acc.x = fmaf(w, xv.x, acc.x);
            acc.y = fmaf(w, xv.y, acc.y);
            acc.z = fmaf(w, xv.z, acc.z);
            acc.w = fmaf(w, xv.w, acc.w);
        }
        *reinterpret_cast<float4*>(&g_a[(size_t)(b*CA + oc)*NPIX + p0 + pg*4]) = acc;
    }
}

// ================= fat kernel: kconv + tgemm0 + apw =========================
#define KCONV_N 512
#define TG0_N   2048
#define APW_N   1024
__global__ __launch_bounds__(256) void fat_kernel(const float* __restrict__ x,
                                                  const float* __restrict__ illu,
                                                  const float* __restrict__ wapw,
                                                  const float* __restrict__ bapw)
{
    int bid = blockIdx.x;
    if (bid < KCONV_N)            kconv_body(bid);
    else if (bid < KCONV_N+TG0_N) tgemm_body<0>(bid - KCONV_N, x, illu, nullptr);
    else                          apw_body(bid - KCONV_N - TG0_N, wapw, bapw);
}

__global__ __launch_bounds__(256) void tgemm1_kernel(float* __restrict__ outp)
{
    tgemm_body<1>(blockIdx.x, nullptr, nullptr, outp);
}

// ================= attention dots + fused norms =============================
__global__ __launch_bounds__(768) void attn_kernel()
{
    __shared__ float a_s[CAH][256];
    int split = blockIdx.x, bh = blockIdx.y;
    int b = bh >> 3, h = bh & 7;
    int tid = threadIdx.x, warp = tid >> 5, lane = tid & 31;
    const float* qp = g_q + (size_t)(b*C + h*CQH + warp)*NPIX;
    const float* kp = g_k + (size_t)(b*C + h*CQH + warp)*NPIX;
    const float* ap = g_a + (size_t)(b*CA + h*CAH)*NPIX;
    int p0 = split * (NPIX / NSPLIT);

    float dq[12], dk[12];
#pragma unroll
    for (int d = 0; d < 12; d++) { dq[d] = 0.f; dk[d] = 0.f; }
    float qq = 0.f, kk = 0.f, aa = 0.f;

    for (int c0 = 0; c0 < NPIX/NSPLIT; c0 += 256) {
        for (int i = tid; i < CAH*256; i += 768) {
            int d = i >> 8, p = i & 255;
            a_s[d][p] = ap[(size_t)d*NPIX + p0 + c0 + p];
        }
        __syncthreads();
#pragma unroll
        for (int hf = 0; hf < 2; hf++) {
            int p = hf*128 + lane*4;
            float4 qv = *(const float4*)&qp[p0 + c0 + p];
            float4 kv = *(const float4*)&kp[p0 + c0 + p];
            qq += qv.x*qv.x + qv.y*qv.y + qv.z*qv.z + qv.w*qv.w;
            kk += kv.x*kv.x + kv.y*kv.y + kv.z*kv.z + kv.w*kv.w;
            if (warp < CAH) {
                float4 av = *(const float4*)&a_s[warp][p];
                aa += av.x*av.x + av.y*av.y + av.z*av.z + av.w*av.w;
            }
#pragma unroll
            for (int d = 0; d < 12; d++) {
                float4 av = *(const float4*)&a_s[d][p];
                dq[d] += qv.x*av.x + qv.y*av.y + qv.z*av.z + qv.w*av.w;
                dk[d] += kv.x*av.x + kv.y*av.y + kv.z*av.z + kv.w*av.w;
            }
        }
        __syncthreads();
    }
#pragma unroll
    for (int off = 16; off; off >>= 1) {
#pragma unroll
        for (int d = 0; d < 12; d++) {
            dq[d] += __shfl_down_sync(0xffffffffu, dq[d], off);
            dk[d] += __shfl_down_sync(0xffffffffu, dk[d], off);
        }
        qq += __shfl_down_sync(0xffffffffu, qq, off);
        kk += __shfl_down_sync(0xffffffffu, kk, off);
        aa += __shfl_down_sync(0xffffffffu, aa, off);
    }
    if (lane == 0) {
        float* out = &g_dotp[((size_t)split*BATCH*HEADS + bh)*DOTP];
#pragma unroll
        for (int d = 0; d < 12; d++) {
            out[warp*12 + d]       = dq[d];
            out[288 + warp*12 + d] = dk[d];
        }
        out[576 + warp] = qq;
        out[600 + warp] = kk;
        if (warp < 12) out[624 + warp] = aa;
    }
}

// ================= combine: norms, softmax, M, W_eff^T (tf32) ===============
__global__ __launch_bounds__(256) void combine_kernel(const float* __restrict__ wo,
                                                      const float* __restrict__ ta,
                                                      const float* __restrict__ tv)
{
    __shared__ float buf[HEADS*DOTP];
    __shared__ float SA[HEADS][CQH][CAH];
    __shared__ float SK[HEADS][CAH][CQH];
    int b = blockIdx.x, tid = threadIdx.x;

    for (int i = tid; i < HEADS*DOTP; i += 256) {
        int h = i / DOTP, e = i - h*DOTP;
        float s = 0.f;
        for (int sp = 0; sp < NSPLIT; sp++)
            s += g_dotp[((size_t)sp*BATCH*HEADS + b*HEADS + h)*DOTP + e];
        buf[i] = s;
    }
    __syncthreads();

    if (tid < HEADS*CQH) {
        int h = tid / CQH, c = tid % CQH;
        const float* B = &buf[h*DOTP];
        float invq = 1.f / fmaxf(sqrtf(B[576 + c]), 1e-12f);
        float tah = ta[h];
        float l[CAH], m = -1e30f;
#pragma unroll
        for (int d = 0; d < CAH; d++) {
            float inva = 1.f / fmaxf(sqrtf(B[624 + d]), 1e-12f);
            l[d] = B[c*12 + d] * invq * inva * tah;
            m = fmaxf(m, l[d]);
        }
        float s = 0.f;
#pragma unroll
        for (int d = 0; d < CAH; d++) { l[d] = expf(l[d] - m); s += l[d]; }
        float inv = 1.f / s;
#pragma unroll
        for (int d = 0; d < CAH; d++) SA[h][c][d] = l[d] * inv;
    }
    if (tid < HEADS*CAH) {
        int h = tid / CAH, d = tid % CAH;
        const float* B = &buf[h*DOTP];
        float inva = 1.f / fmaxf(sqrtf(B[624 + d]), 1e-12f);
        float tvh = tv[h];
        float l[CQH], m = -1e30f;
#pragma unroll
        for (int c = 0; c < CQH; c++) {
            float invk = 1.f / fmaxf(sqrtf(B[600 + c]), 1e-12f);
            l[c] = B[288 + c*12 + d] * invk * inva * tvh;
            m = fmaxf(m, l[c]);
        }
        float s = 0.f;
#pragma unroll
        for (int c = 0; c < CQH; c++) { l[c] = expf(l[c] - m); s += l[c]; }
        float inv = 1.f / s;
#pragma unroll
        for (int c = 0; c < CQH; c++) SK[h][d][c] = l[c] * inv;
    }
    __syncthreads();

    float* M = buf;
    for (int i = tid; i < HEADS*CQH*CQH; i += 256) {
        int h = i / (CQH*CQH), r = (i / CQH) % CQH, j = i % CQH;
        float s = 0.f;
#pragma unroll
        for (int d = 0; d < CAH; d++) s = fmaf(SA[h][r][d], SK[h][d][j], s);
        M[(h*CQH + r)*CQH + j] = s;
    }
    __syncthreads();

    for (int i = tid; i < C*C; i += 256) {
        int cv = i / C, o = i % C;
        int hv = cv / CQH, j = cv % CQH;
        float s = 0.f;
#pragma unroll
        for (int k = 0; k < CQH; k++)
            s = fmaf(wo[o*C + hv*CQH + k], M[(hv*CQH + k)*CQH + j], s);
        g_weffT[(size_t)b*C*C + i] = f2tf(s);
    }
}

// ================= launch ===================================================
extern "C" void kernel_launch(void* const* d_in, const int* in_sizes, int n_in,
                              void* d_out, int out_size)
{
    const float* x    = (const float*)d_in[0];
    const float* illu = (const float*)d_in[1];
    const float* wq   = (const float*)d_in[2];
    const float* wk   = (const float*)d_in[3];
    const float* wadw = (const float*)d_in[4];
    const float* wapw = (const float*)d_in[5];
    const float* bapw = (const float*)d_in[6];
    const float* wv   = (const float*)d_in[7];
    const float* wo   = (const float*)d_in[8];
    const float* ta   = (const float*)d_in[9];
    const float* tv   = (const float*)d_in[10];
    float* out = (float*)d_out;

    const int fat_smem = (2*KC_AS + 2*KC_BS + KKDIM) * 4;   // 92928
    const int tg_smem  = (2*KC_AS + 2*KC_BS) * 4;           // 86016
    cudaFuncSetAttribute(fat_kernel, cudaFuncAttributeMaxDynamicSharedMemorySize, fat_smem);
    cudaFuncSetAttribute(tgemm1_kernel, cudaFuncAttributeMaxDynamicSharedMemorySize, tg_smem);

    preproc_kernel<<<SDQ_N + ZP_N + PREP_N, 256>>>(x, wq, wadw, wk, wv);
    fat_kernel    <<<KCONV_N + TG0_N + APW_N, 256, fat_smem>>>(x, illu, wapw, bapw);
    attn_kernel   <<<dim3(NSPLIT, BATCH*HEADS), 768>>>();
    combine_kernel<<<BATCH, 256>>>(wo, ta, tv);
    tgemm1_kernel <<<TG0_N, 256, tg_smem>>>(out);
}

// round 7
// speedup vs baseline: 3.7570x; 1.3970x over previous
#include <cuda_runtime.h>
#include <cstdint>

#define BATCH 4
#define C 192
#define HW 256
#define HO 128
#define NPIX (HO*HO)      // 16384
#define NPIXF (HW*HW)     // 65536
#define HEADS 8
#define CQH 24
#define CAH 12
#define CA 96
#define KKDIM (C*9)       // 1728
#define PLANE (129*132)
#define NSPLIT 8
#define DOTP 640
#define KC_AS 6400
#define KC_BS 4352

// ---------------- scratch ----------------
__device__ float    g_q[BATCH*C*NPIX];
__device__ float    g_k[BATCH*C*NPIX];
__device__ float    g_adw[BATCH*C*NPIX];
__device__ float    g_a[BATCH*CA*NPIX];
__device__ unsigned g_v[(size_t)BATCH*C*NPIXF];      // tf32 bits
__device__ unsigned g_xp[(size_t)BATCH*C*4*PLANE];   // tf32 bits
__device__ unsigned g_wkT[KKDIM*C];                  // tf32 bits
__device__ unsigned g_wvT[C*C];                      // tf32 bits
__device__ unsigned g_weffT[BATCH*C*C];              // tf32 bits
__device__ float    g_dotp[(size_t)NSPLIT*BATCH*HEADS*DOTP];

// ---------------- helpers ----------------
__device__ __forceinline__ unsigned f2tf(float f){
    unsigned r; asm("cvt.rna.tf32.f32 %0, %1;" : "=r"(r) : "f"(f)); return r;
}
__device__ __forceinline__ void mma_tf32(float& c0, float& c1, float& c2, float& c3,
                                         unsigned a0, unsigned a1, unsigned a2, unsigned a3,
                                         unsigned b0, unsigned b1){
    asm volatile("mma.sync.aligned.m16n8k8.row.col.f32.tf32.tf32.f32 "
                 "{%0,%1,%2,%3},{%4,%5,%6,%7},{%8,%9},{%0,%1,%2,%3};"
                 : "+f"(c0), "+f"(c1), "+f"(c2), "+f"(c3)
                 : "r"(a0), "r"(a1), "r"(a2), "r"(a3), "r"(b0), "r"(b1));
}
__device__ __forceinline__ void cpa16(void* s, const void* g){
    unsigned sa = (unsigned)__cvta_generic_to_shared(s);
    asm volatile("cp.async.ca.shared.global [%0],[%1],16;" :: "r"(sa), "l"(g));
}
__device__ __forceinline__ void cpa4(void* s, const void* g){
    unsigned sa = (unsigned)__cvta_generic_to_shared(s);
    asm volatile("cp.async.ca.shared.global [%0],[%1],4;" :: "r"(sa), "l"(g));
}
#define CP_COMMIT asm volatile("cp.async.commit_group;")

// ================= preproc: prep + zeropad + sdq (fused launch) =============
__device__ void prep_body(int bid, const float* __restrict__ wk,
                          const float* __restrict__ wv)
{
    int i = bid * 256 + threadIdx.x;
    if (i < KKDIM*C) {
        int k = i / C, oc = i % C;
        g_wkT[i] = f2tf(wk[oc*KKDIM + k]);
    } else {
        int j = i - KKDIM*C;
        if (j < C*C) {
            int ic = j / C, oc = j % C;
            g_wvT[j] = f2tf(wv[oc*C + ic]);
        }
    }
}

__device__ void zeropad_body(int bid)
{
    size_t base = (size_t)bid * PLANE;
    for (int i = threadIdx.x; i < 260; i += 256) {
        if (i < 132) g_xp[base + i] = 0u;
        else         g_xp[base + (i - 131)*132] = 0u;
    }
}

__device__ void sdq_body(int bid, const float* __restrict__ x,
                         const float* __restrict__ wq,
                         const float* __restrict__ wadw)
{
    __shared__ float xs[66][68];
    int tile = bid & 15;
    int bc   = bid >> 4;
    int c    = bc % C;
    int oy0 = (tile >> 2) * 32, ox0 = (tile & 3) * 32;
    int iy0 = 2*oy0 - 1, ix0 = 2*ox0 - 1;
    const float* xp = x + (size_t)bc * NPIXF;
    int tid = threadIdx.x;

    for (int i = tid; i < 66*66; i += 256) {
        int r = i / 66, cc = i - r*66;
        int iy = iy0 + r, ix = ix0 + cc;
        float v = 0.f;
        if (iy >= 0 && iy < HW && ix >= 0 && ix < HW) v = xp[iy*HW + ix];
        xs[r][cc] = v;
    }
    __syncthreads();

    size_t pbase = (size_t)bc * 4 * PLANE;
    for (int i = tid; i < 4096; i += 256) {
        int ly = i >> 6, lx = i & 63;
        int ph = ((ly & 1) << 1) | (lx & 1);
        g_xp[pbase + (size_t)ph*PLANE + (oy0 + (ly>>1) + 1)*132 + ox0 + (lx>>1) + 1]
            = f2tf(xs[ly + 1][lx + 1]);
    }

    float wqr[9], war[9];
#pragma unroll
    for (int i = 0; i < 9; i++) { wqr[i] = wq[c*9+i]; war[i] = wadw[c*9+i]; }
#pragma unroll
    for (int j = 0; j < 4; j++) {
        int oyl = (tid >> 5) + j*8, oxl = tid & 31;
        float aq = 0.f, aa = 0.f;
#pragma unroll
        for (int ky = 0; ky < 3; ky++)
#pragma unroll
            for (int kx = 0; kx < 3; kx++) {
                float v = xs[2*oyl + ky][2*oxl + kx];
                aq = fmaf(wqr[ky*3+kx], v, aq);
                aa = fmaf(war[ky*3+kx], v, aa);
            }
        size_t o = (size_t)bc * NPIX + (oy0 + oyl)*HO + ox0 + oxl;
        g_q[o] = aq;
        g_adw[o] = aa;
    }
}

#define PREP_N 1440
#define ZP_N   (BATCH*C*4)
#define SDQ_N  (16*BATCH*C)
__global__ __launch_bounds__(256) void preproc_kernel(const float* __restrict__ x,
                                                      const float* __restrict__ wq,
                                                      const float* __restrict__ wadw,
                                                      const float* __restrict__ wk,
                                                      const float* __restrict__ wv)
{
    int bid = blockIdx.x;
    if (bid < SDQ_N)               sdq_body(bid, x, wq, wadw);
    else if (bid < SDQ_N + ZP_N)   zeropad_body(bid - SDQ_N);
    else                           prep_body(bid - SDQ_N - ZP_N, wk, wv);
}

// ================= kconv body: pipelined tf32 implicit GEMM =================
__device__ __forceinline__ void kconv_fillB(unsigned* dstBase, const int* rowoff,
                                            int k0, int tid)
{
    for (int i = tid; i < 1024; i += 256) {
        int kk = i >> 5, g4 = i & 31;
        int pr = g4 >> 2, pc = (g4 & 3) * 4;
        int ro = rowoff[k0 + kk];
        const unsigned* gp = &g_xp[ro + pr*132 + pc];
        unsigned* sp = &dstBase[kk*136 + pr*16 + pc];
        if ((ro & 3) == 0) {
            cpa16(sp, gp);
        } else {
            cpa4(sp,     gp);
            cpa4(sp + 1, gp + 1);
            cpa4(sp + 2, gp + 2);
            cpa4(sp + 3, gp + 3);
        }
    }
}

__device__ void kconv_body(int bid)
{
    extern __shared__ unsigned smm[];
    unsigned* Asm = smm;
    unsigned* Bsm = smm + 2*KC_AS;
    int* rowoff = (int*)(smm + 2*KC_AS + 2*KC_BS);

    int b = bid >> 7;
    int tile = bid & 127;
    int oy0 = (tile >> 3) * 8, ox0 = (tile & 7) * 16;
    int tid = threadIdx.x;
    int warp = tid >> 5, lane = tid & 31;
    int wm = warp >> 1, wn = warp & 1;
    int g = lane >> 2, tg = lane & 3;

    for (int k = tid; k < KKDIM; k += 256) {
        int ic = k / 9, t = k - ic*9;
        int ky = t / 3, kx = t - ky*3;
        int py = (ky == 1) ? 0 : 1, px = (kx == 1) ? 0 : 1;
        int dy = (ky == 0) ? 0 : 1, dx = (kx == 0) ? 0 : 1;
        rowoff[k] = ((b*C + ic)*4 + py*2 + px)*PLANE + (oy0+dy)*132 + (ox0+dx);
    }
    __syncthreads();

    float acc[3][8][4];
#pragma unroll
    for (int mf = 0; mf < 3; mf++)
#pragma unroll
        for (int nf = 0; nf < 8; nf++)
#pragma unroll
            for (int q = 0; q < 4; q++) acc[mf][nf][q] = 0.f;

    for (int i = tid; i < 1536; i += 256) {
        int kk = i / 48, m4 = (i % 48) * 4;
        cpa16(&Asm[kk*200 + m4], &g_wkT[kk*C + m4]);
    }
    kconv_fillB(Bsm, rowoff, 0, tid);
    CP_COMMIT;

#pragma unroll 1
    for (int c2 = 0; c2 < 54; c2++) {
        int p = c2 & 1;
        if (c2 + 1 < 54) {
            int q2 = p ^ 1;
            int k0 = (c2 + 1) * 32;
            for (int i = tid; i < 1536; i += 256) {
                int kk = i / 48, m4 = (i % 48) * 4;
                cpa16(&Asm[q2*KC_AS + kk*200 + m4], &g_wkT[(k0+kk)*C + m4]);
            }
            kconv_fillB(&Bsm[q2*KC_BS], rowoff, k0, tid);
            CP_COMMIT;
            asm volatile("cp.async.wait_group 1;");
        } else {
            asm volatile("cp.async.wait_group 0;");
        }
        __syncthreads();

        const unsigned* Ab = &Asm[p*KC_AS];
        const unsigned* Bb = &Bsm[p*KC_BS];
#pragma unroll
        for (int k8 = 0; k8 < 4; k8++) {
            int kb = k8 * 8;
            unsigned a[3][4], bb[8][2];
#pragma unroll
            for (int mf = 0; mf < 3; mf++) {
                int mb = wm*48 + mf*16 + g;
                a[mf][0] = Ab[(kb+tg)*200 + mb];     a[mf][1] = Ab[(kb+tg)*200 + mb + 8];
                a[mf][2] = Ab[(kb+tg+4)*200 + mb];   a[mf][3] = Ab[(kb+tg+4)*200 + mb + 8];
            }
#pragma unroll
            for (int nf = 0; nf < 8; nf++) {
                int nb = wn*64 + nf*8 + g;
                bb[nf][0] = Bb[(kb+tg)*136 + nb];    bb[nf][1] = Bb[(kb+tg+4)*136 + nb];
            }
#pragma unroll
            for (int mf = 0; mf < 3; mf++)
#pragma unroll
                for (int nf = 0; nf < 8; nf++)
                    mma_tf32(acc[mf][nf][0], acc[mf][nf][1], acc[mf][nf][2], acc[mf][nf][3],
                             a[mf][0], a[mf][1], a[mf][2], a[mf][3], bb[nf][0], bb[nf][1]);
        }
        __syncthreads();
    }

#pragma unroll
    for (int mf = 0; mf < 3; mf++)
#pragma unroll
        for (int nf = 0; nf < 8; nf++) {
            int m = wm*48 + mf*16 + g;
            int n = wn*64 + nf*8 + tg*2;
            int oy = oy0 + (n >> 4), ox = ox0 + (n & 15);
            *(float2*)&g_k[(size_t)(b*C + m)*NPIX + oy*HO + ox] =
                make_float2(acc[mf][nf][0], acc[mf][nf][1]);
            *(float2*)&g_k[(size_t)(b*C + m + 8)*NPIX + oy*HO + ox] =
                make_float2(acc[mf][nf][2], acc[mf][nf][3]);
        }
}

// ================= tgemm body: M=192 x N=128, K=192 =========================
template<int MODE>
__device__ void tgemm_body(int bid, const float* __restrict__ xin,
                           const float* __restrict__ illu,
                           float* __restrict__ outp)
{
    extern __shared__ unsigned smm[];
    unsigned* Asm = smm;
    unsigned* Bsm = smm + 2*KC_AS;

    int b = bid >> 9;
    int n0 = (bid & 511) * 128;
    const unsigned* A = (MODE == 0) ? g_wvT : (g_weffT + (size_t)b*C*C);
    const float* Bf = (MODE == 0) ? (xin + (size_t)b*C*NPIXF) : nullptr;
    const unsigned* Bu = (MODE == 1) ? (g_v + (size_t)b*C*NPIXF) : nullptr;
    const float* Ib = (MODE == 0) ? (illu + (size_t)b*C*NPIXF) : nullptr;

    int tid = threadIdx.x;
    int warp = tid >> 5, lane = tid & 31;
    int wm = warp >> 1, wn = warp & 1;
    int g = lane >> 2, tg = lane & 3;

    float acc[3][8][4];
#pragma unroll
    for (int mf = 0; mf < 3; mf++)
#pragma unroll
        for (int nf = 0; nf < 8; nf++)
#pragma unroll
            for (int q = 0; q < 4; q++) acc[mf][nf][q] = 0.f;

    for (int i = tid; i < 1536; i += 256) {
        int kk = i / 48, m4 = (i % 48) * 4;
        cpa16(&Asm[kk*200 + m4], &A[kk*C + m4]);
    }
    if (MODE == 1) {
        for (int j = 0; j < 4; j++) {
            int i = tid + j*256;
            int kk = i >> 5, n4 = (i & 31) * 4;
            cpa16(&Bsm[kk*136 + n4], &Bu[(size_t)kk*NPIXF + n0 + n4]);
        }
    }
    CP_COMMIT;
    if (MODE == 0) {
        float4 t0[4];
#pragma unroll
        for (int j = 0; j < 4; j++) {
            int i = tid + j*256;
            int kk = i >> 5, n4 = (i & 31) * 4;
            t0[j] = *(const float4*)&Bf[(size_t)kk*NPIXF + n0 + n4];
        }
#pragma unroll
        for (int j = 0; j < 4; j++) {
            int i = tid + j*256;
            int kk = i >> 5, n4 = (i & 31) * 4;
            *(uint4*)&Bsm[kk*136 + n4] =
                make_uint4(f2tf(t0[j].x), f2tf(t0[j].y), f2tf(t0[j].z), f2tf(t0[j].w));
        }
    }

    float4 tmp[4];
#pragma unroll 1
    for (int c2 = 0; c2 < 6; c2++) {
        int p = c2 & 1;
        int q2 = p ^ 1;
        if (c2 + 1 < 6) {
            int k0 = (c2 + 1) * 32;
            for (int i = tid; i < 1536; i += 256) {
                int kk = i / 48, m4 = (i % 48) * 4;
                cpa16(&Asm[q2*KC_AS + kk*200 + m4], &A[(k0+kk)*C + m4]);
            }
            if (MODE == 1) {
#pragma unroll
                for (int j = 0; j < 4; j++) {
                    int i = tid + j*256;
                    int kk = i >> 5, n4 = (i & 31) * 4;
                    cpa16(&Bsm[q2*KC_BS + kk*136 + n4],
                          &Bu[(size_t)(k0+kk)*NPIXF + n0 + n4]);
                }
            }
            CP_COMMIT;
            if (MODE == 0) {
#pragma unroll
                for (int j = 0; j < 4; j++) {
                    int i = tid + j*256;
                    int kk = i >> 5, n4 = (i & 31) * 4;
                    tmp[j] = *(const float4*)&Bf[(size_t)(k0+kk)*NPIXF + n0 + n4];
                }
            }
            asm volatile("cp.async.wait_group 1;");
        } else {
            asm volatile("cp.async.wait_group 0;");
        }
        __syncthreads();

        const unsigned* Ab = &Asm[p*KC_AS];
        const unsigned* Bb = &Bsm[p*KC_BS];
#pragma unroll
        for (int k8 = 0; k8 < 4; k8++) {
            int kb = k8 * 8;
            unsigned a[3][4], bb[8][2];
#pragma unroll
            for (int mf = 0; mf < 3; mf++) {
                int mb = wm*48 + mf*16 + g;
                a[mf][0] = Ab[(kb+tg)*200 + mb];     a[mf][1] = Ab[(kb+tg)*200 + mb + 8];
                a[mf][2] = Ab[(kb+tg+4)*200 + mb];   a[mf][3] = Ab[(kb+tg+4)*200 + mb + 8];
            }
#pragma unroll
            for (int nf = 0; nf < 8; nf++) {
                int nb = wn*64 + nf*8 + g;
                bb[nf][0] = Bb[(kb+tg)*136 + nb];    bb[nf][1] = Bb[(kb+tg+4)*136 + nb];
            }
#pragma unroll
            for (int mf = 0; mf < 3; mf++)
#pragma unroll
                for (int nf = 0; nf < 8; nf++)
                    mma_tf32(acc[mf][nf][0], acc[mf][nf][1], acc[mf][nf][2], acc[mf][nf][3],
                             a[mf][0], a[mf][1], a[mf][2], a[mf][3], bb[nf][0], bb[nf][1]);
        }
        if (MODE == 0 && c2 + 1 < 6) {
#pragma unroll
            for (int j = 0; j < 4; j++) {
                int i = tid + j*256;
                int kk = i >> 5, n4 = (i & 31) * 4;
                *(uint4*)&Bsm[q2*KC_BS + kk*136 + n4] =
                    make_uint4(f2tf(tmp[j].x), f2tf(tmp[j].y), f2tf(tmp[j].z), f2tf(tmp[j].w));
            }
        }
        __syncthreads();
    }

#pragma unroll
    for (int mf = 0; mf < 3; mf++)
#pragma unroll
        for (int nf = 0; nf < 8; nf++) {
            int m = wm*48 + mf*16 + g;
            int n = n0 + wn*64 + nf*8 + tg*2;
            if (MODE == 0) {
                float2 i0 = *(const float2*)&Ib[(size_t)m*NPIXF + n];
                float2 i1 = *(const float2*)&Ib[(size_t)(m+8)*NPIXF + n];
                unsigned* O = g_v + (size_t)b*C*NPIXF;
                *(uint2*)&O[(size_t)m*NPIXF + n] =
                    make_uint2(f2tf(acc[mf][nf][0]*i0.x), f2tf(acc[mf][nf][1]*i0.y));
                *(uint2*)&O[(size_t)(m+8)*NPIXF + n] =
                    make_uint2(f2tf(acc[mf][nf][2]*i1.x), f2tf(acc[mf][nf][3]*i1.y));
            } else {
                float* O = outp + (size_t)b*C*NPIXF;
                *(float2*)&O[(size_t)m*NPIXF + n] =
                    make_float2(acc[mf][nf][0], acc[mf][nf][1]);
                *(float2*)&O[(size_t)(m+8)*NPIXF + n] =
                    make_float2(acc[mf][nf][2], acc[mf][nf][3]);
            }
        }
}

// ================= apw body: pointwise 192->96 (+bias) ======================
__device__ void apw_body(int bid, const float* __restrict__ wapw,
                         const float* __restrict__ bapw)
{
    extern __shared__ unsigned smm[];
    float* s = (float*)smm;               // C*64 floats = 48KB
    int b = bid >> 8;
    int p0 = (bid & 255) * 64;
    for (int i = threadIdx.x; i < C*64; i += 256) {
        int cc = i >> 6, pp = i & 63;
        s[i] = g_adw[(size_t)(b*C + cc)*NPIX + p0 + pp];
    }
    __syncthreads();
    int pg  = threadIdx.x & 15;
    int ocb = threadIdx.x >> 4;
    for (int oc = ocb; oc < CA; oc += 16) {
        float bsv = bapw[oc];
        float4 acc = make_float4(bsv, bsv, bsv, bsv);
        for (int ic = 0; ic < C; ic++) {
            float w = __ldg(&wapw[oc*C + ic]);
            float4 xv = *reinterpret_cast<const float4*>(&s[ic*64 + pg*4]);
            acc.x = fmaf(w, xv.x, acc.x);
            acc.y = fmaf(w, xv.y, acc.y);
            acc.z = fmaf(w, xv.z, acc.z);
            acc.w = fmaf(w, xv.w, acc.w);
        }
        *reinterpret_cast<float4*>(&g_a[(size_t)(b*CA + oc)*NPIX + p0 + pg*4]) = acc;
    }
}

// ================= fat kernel: kconv + tgemm0 + apw =========================
#define KCONV_N 512
#define TG0_N   2048
#define APW_N   1024
__global__ __launch_bounds__(256) void fat_kernel(const float* __restrict__ x,
                                                  const float* __restrict__ illu,
                                                  const float* __restrict__ wapw,
                                                  const float* __restrict__ bapw)
{
    int bid = blockIdx.x;
    if (bid < KCONV_N)            kconv_body(bid);
    else if (bid < KCONV_N+TG0_N) tgemm_body<0>(bid - KCONV_N, x, illu, nullptr);
    else                          apw_body(bid - KCONV_N - TG0_N, wapw, bapw);
}

__global__ __launch_bounds__(256) void tgemm1_kernel(float* __restrict__ outp)
{
    tgemm_body<1>(blockIdx.x, nullptr, nullptr, outp);
}

// ================= attention dots + fused norms =============================
__global__ __launch_bounds__(768) void attn_kernel()
{
    __shared__ float a_s[CAH][256];
    int split = blockIdx.x, bh = blockIdx.y;
    int b = bh >> 3, h = bh & 7;
    int tid = threadIdx.x, warp = tid >> 5, lane = tid & 31;
    const float* qp = g_q + (size_t)(b*C + h*CQH + warp)*NPIX;
    const float* kp = g_k + (size_t)(b*C + h*CQH + warp)*NPIX;
    const float* ap = g_a + (size_t)(b*CA + h*CAH)*NPIX;
    int p0 = split * (NPIX / NSPLIT);

    float dq[12], dk[12];
#pragma unroll
    for (int d = 0; d < 12; d++) { dq[d] = 0.f; dk[d] = 0.f; }
    float qq = 0.f, kk = 0.f, aa = 0.f;

    for (int c0 = 0; c0 < NPIX/NSPLIT; c0 += 256) {
        for (int i = tid; i < CAH*256; i += 768) {
            int d = i >> 8, p = i & 255;
            a_s[d][p] = ap[(size_t)d*NPIX + p0 + c0 + p];
        }
        __syncthreads();
#pragma unroll
        for (int hf = 0; hf < 2; hf++) {
            int p = hf*128 + lane*4;
            float4 qv = *(const float4*)&qp[p0 + c0 + p];
            float4 kv = *(const float4*)&kp[p0 + c0 + p];
            qq += qv.x*qv.x + qv.y*qv.y + qv.z*qv.z + qv.w*qv.w;
            kk += kv.x*kv.x + kv.y*kv.y + kv.z*kv.z + kv.w*kv.w;
            if (warp < CAH) {
                float4 av = *(const float4*)&a_s[warp][p];
                aa += av.x*av.x + av.y*av.y + av.z*av.z + av.w*av.w;
            }
#pragma unroll
            for (int d = 0; d < 12; d++) {
                float4 av = *(const float4*)&a_s[d][p];
                dq[d] += qv.x*av.x + qv.y*av.y + qv.z*av.z + qv.w*av.w;
                dk[d] += kv.x*av.x + kv.y*av.y + kv.z*av.z + kv.w*av.w;
            }
        }
        __syncthreads();
    }
#pragma unroll
    for (int off = 16; off; off >>= 1) {
#pragma unroll
        for (int d = 0; d < 12; d++) {
            dq[d] += __shfl_down_sync(0xffffffffu, dq[d], off);
            dk[d] += __shfl_down_sync(0xffffffffu, dk[d], off);
        }
        qq += __shfl_down_sync(0xffffffffu, qq, off);
        kk += __shfl_down_sync(0xffffffffu, kk, off);
        aa += __shfl_down_sync(0xffffffffu, aa, off);
    }
    if (lane == 0) {
        float* out = &g_dotp[((size_t)split*BATCH*HEADS + bh)*DOTP];
#pragma unroll
        for (int d = 0; d < 12; d++) {
            out[warp*12 + d]       = dq[d];
            out[288 + warp*12 + d] = dk[d];
        }
        out[576 + warp] = qq;
        out[600 + warp] = kk;
        if (warp < 12) out[624 + warp] = aa;
    }
}

// ================= combine: norms, softmax, M, W_eff^T slice (tf32) =========
// grid (16, BATCH): every block redundantly computes softmax+M (cheap),
// then writes a 1/16 slice of W_eff^T -> 64 active blocks instead of 4.
#define WSLICE (C*C/16)      // 2304
__global__ __launch_bounds__(256) void combine_kernel(const float* __restrict__ wo,
                                                      const float* __restrict__ ta,
                                                      const float* __restrict__ tv)
{
    __shared__ float buf[HEADS*DOTP];
    __shared__ float SA[HEADS][CQH][CAH];
    __shared__ float SK[HEADS][CAH][CQH];
    int slice = blockIdx.x, b = blockIdx.y, tid = threadIdx.x;

    for (int i = tid; i < HEADS*DOTP; i += 256) {
        int h = i / DOTP, e = i - h*DOTP;
        float s = 0.f;
#pragma unroll
        for (int sp = 0; sp < NSPLIT; sp++)
            s += g_dotp[((size_t)sp*BATCH*HEADS + b*HEADS + h)*DOTP + e];
        buf[i] = s;
    }
    __syncthreads();

    if (tid < HEADS*CQH) {
        int h = tid / CQH, c = tid % CQH;
        const float* B = &buf[h*DOTP];
        float invq = 1.f / fmaxf(sqrtf(B[576 + c]), 1e-12f);
        float tah = ta[h];
        float l[CAH], m = -1e30f;
#pragma unroll
        for (int d = 0; d < CAH; d++) {
            float inva = 1.f / fmaxf(sqrtf(B[624 + d]), 1e-12f);
            l[d] = B[c*12 + d] * invq * inva * tah;
            m = fmaxf(m, l[d]);
        }
        float s = 0.f;
#pragma unroll
        for (int d = 0; d < CAH; d++) { l[d] = expf(l[d] - m); s += l[d]; }
        float inv = 1.f / s;
#pragma unroll
        for (int d = 0; d < CAH; d++) SA[h][c][d] = l[d] * inv;
    }
    if (tid < HEADS*CAH) {
        int h = tid / CAH, d = tid % CAH;
        const float* B = &buf[h*DOTP];
        float inva = 1.f / fmaxf(sqrtf(B[624 + d]), 1e-12f);
        float tvh = tv[h];
        float l[CQH], m = -1e30f;
#pragma unroll
        for (int c = 0; c < CQH; c++) {
            float invk = 1.f / fmaxf(sqrtf(B[600 + c]), 1e-12f);
            l[c] = B[288 + c*12 + d] * invk * inva * tvh;
            m = fmaxf(m, l[c]);
        }
        float s = 0.f;
#pragma unroll
        for (int c = 0; c < CQH; c++) { l[c] = expf(l[c] - m); s += l[c]; }
        float inv = 1.f / s;
#pragma unroll
        for (int c = 0; c < CQH; c++) SK[h][d][c] = l[c] * inv;
    }
    __syncthreads();

    float* M = buf;
    for (int i = tid; i < HEADS*CQH*CQH; i += 256) {
        int h = i / (CQH*CQH), r = (i / CQH) % CQH, j = i % CQH;
        float s = 0.f;
#pragma unroll
        for (int d = 0; d < CAH; d++) s = fmaf(SA[h][r][d], SK[h][d][j], s);
        M[(h*CQH + r)*CQH + j] = s;
    }
    __syncthreads();

    // this block's 1/16 slice of W_eff^T ([cv][o] layout)
    int base = slice * WSLICE;
#pragma unroll
    for (int jj = 0; jj < WSLICE/256; jj++) {
        int i = base + jj*256 + tid;
        int cv = i / C, o = i % C;
        int hv = cv / CQH, j = cv % CQH;
        float s = 0.f;
#pragma unroll
        for (int k = 0; k < CQH; k++)
            s = fmaf(wo[o*C + hv*CQH + k], M[(hv*CQH + k)*CQH + j], s);
        g_weffT[(size_t)b*C*C + i] = f2tf(s);
    }
}

// ================= launch ===================================================
extern "C" void kernel_launch(void* const* d_in, const int* in_sizes, int n_in,
                              void* d_out, int out_size)
{
    const float* x    = (const float*)d_in[0];
    const float* illu = (const float*)d_in[1];
    const float* wq   = (const float*)d_in[2];
    const float* wk   = (const float*)d_in[3];
    const float* wadw = (const float*)d_in[4];
    const float* wapw = (const float*)d_in[5];
    const float* bapw = (const float*)d_in[6];
    const float* wv   = (const float*)d_in[7];
    const float* wo   = (const float*)d_in[8];
    const float* ta   = (const float*)d_in[9];
    const float* tv   = (const float*)d_in[10];
    float* out = (float*)d_out;

    const int fat_smem = (2*KC_AS + 2*KC_BS + KKDIM) * 4;   // 92928
    const int tg_smem  = (2*KC_AS + 2*KC_BS) * 4;           // 86016
    cudaFuncSetAttribute(fat_kernel, cudaFuncAttributeMaxDynamicSharedMemorySize, fat_smem);
    cudaFuncSetAttribute(tgemm1_kernel, cudaFuncAttributeMaxDynamicSharedMemorySize, tg_smem);

    preproc_kernel<<<SDQ_N + ZP_N + PREP_N, 256>>>(x, wq, wadw, wk, wv);
    fat_kernel    <<<KCONV_N + TG0_N + APW_N, 256, fat_smem>>>(x, illu, wapw, bapw);
    attn_kernel   <<<dim3(NSPLIT, BATCH*HEADS), 768>>>();
    combine_kernel<<<dim3(16, BATCH), 256>>>(wo, ta, tv);
    tgemm1_kernel <<<TG0_N, 256, tg_smem>>>(out);
}

// round 9
// speedup vs baseline: 3.8593x; 1.0272x over previous
#include <cuda_runtime.h>
#include <cstdint>

#define BATCH 4
#define C 192
#define HW 256
#define HO 128
#define NPIX (HO*HO)      // 16384
#define NPIXF (HW*HW)     // 65536
#define HEADS 8
#define CQH 24
#define CAH 12
#define CA 96
#define KKDIM (C*9)       // 1728
#define PLANE (129*132)
#define NSPLIT 16
#define DOTP 640
#define KC_AS 6400
#define KC_BS 4352

// ---------------- scratch ----------------
__device__ float    g_q[BATCH*C*NPIX];
__device__ float    g_k[BATCH*C*NPIX];
__device__ float    g_adw[BATCH*C*NPIX];
__device__ float    g_a[BATCH*CA*NPIX];
__device__ unsigned g_v[(size_t)BATCH*C*NPIXF];      // tf32 bits
__device__ unsigned g_xp[(size_t)BATCH*C*4*PLANE];   // tf32 bits
__device__ unsigned g_wkT[KKDIM*C];                  // tf32 bits
__device__ unsigned g_wvT[C*C];                      // tf32 bits
__device__ unsigned g_weffT[BATCH*C*C];              // tf32 bits
__device__ float    g_dotp[(size_t)NSPLIT*BATCH*HEADS*DOTP];

// ---------------- helpers ----------------
__device__ __forceinline__ unsigned f2tf(float f){
    unsigned r; asm("cvt.rna.tf32.f32 %0, %1;" : "=r"(r) : "f"(f)); return r;
}
__device__ __forceinline__ void mma_tf32(float& c0, float& c1, float& c2, float& c3,
                                         unsigned a0, unsigned a1, unsigned a2, unsigned a3,
                                         unsigned b0, unsigned b1){
    asm volatile("mma.sync.aligned.m16n8k8.row.col.f32.tf32.tf32.f32 "
                 "{%0,%1,%2,%3},{%4,%5,%6,%7},{%8,%9},{%0,%1,%2,%3};"
                 : "+f"(c0), "+f"(c1), "+f"(c2), "+f"(c3)
                 : "r"(a0), "r"(a1), "r"(a2), "r"(a3), "r"(b0), "r"(b1));
}
__device__ __forceinline__ void cpa16(void* s, const void* g){
    unsigned sa = (unsigned)__cvta_generic_to_shared(s);
    asm volatile("cp.async.ca.shared.global [%0],[%1],16;" :: "r"(sa), "l"(g));
}
__device__ __forceinline__ void cpa4(void* s, const void* g){
    unsigned sa = (unsigned)__cvta_generic_to_shared(s);
    asm volatile("cp.async.ca.shared.global [%0],[%1],4;" :: "r"(sa), "l"(g));
}
#define CP_COMMIT asm volatile("cp.async.commit_group;")

// ================= preproc: prep + zeropad + sdq (fused launch) =============
__device__ void prep_body(int bid, const float* __restrict__ wk,
                          const float* __restrict__ wv)
{
    int i = bid * 256 + threadIdx.x;
    if (i < KKDIM*C) {
        int k = i / C, oc = i % C;
        g_wkT[i] = f2tf(wk[oc*KKDIM + k]);
    } else {
        int j = i - KKDIM*C;
        if (j < C*C) {
            int ic = j / C, oc = j % C;
            g_wvT[j] = f2tf(wv[oc*C + ic]);
        }
    }
}

__device__ void zeropad_body(int bid)
{
    size_t base = (size_t)bid * PLANE;
    for (int i = threadIdx.x; i < 260; i += 256) {
        if (i < 132) g_xp[base + i] = 0u;
        else         g_xp[base + (i - 131)*132] = 0u;
    }
}

// xs layout: cols 0..63 hold logical cc = 1..64 (ix = ix0+1+col, 16B-aligned loads),
//            col 64 holds logical cc = 0 (ix = ix0). Logical col 65 is never used.
__device__ void sdq_body(int bid, const float* __restrict__ x,
                         const float* __restrict__ wq,
                         const float* __restrict__ wadw)
{
    __shared__ float xs[66][68];
    int tile = bid & 15;
    int bc   = bid >> 4;
    int c    = bc % C;
    int oy0 = (tile >> 2) * 32, ox0 = (tile & 3) * 32;
    int iy0 = 2*oy0 - 1, ix0 = 2*ox0 - 1;
    int ixA = ix0 + 1;                    // = 2*ox0, 16B-aligned
    const float* xp = x + (size_t)bc * NPIXF;
    int tid = threadIdx.x;

    // interior: 66 rows x 16 float4
    for (int i = tid; i < 66*16; i += 256) {
        int r = i >> 4, seg = i & 15;
        int iy = iy0 + r;
        float4 v = make_float4(0.f, 0.f, 0.f, 0.f);
        if (iy >= 0 && iy < HW) v = *(const float4*)&xp[iy*HW + ixA + seg*4];
        *(float4*)&xs[r][seg*4] = v;
    }
    // left edge column (logical cc = 0)
    if (tid < 66) {
        int iy = iy0 + tid;
        float v = 0.f;
        if (iy >= 0 && iy < HW && ix0 >= 0) v = xp[iy*HW + ix0];
        xs[tid][64] = v;
    }
    __syncthreads();

    // parity-plane writes: logical (ly+1, lx+1) -> phys col lx
    size_t pbase = (size_t)bc * 4 * PLANE;
    for (int i = tid; i < 4096; i += 256) {
        int ly = i >> 6, lx = i & 63;
        int ph = ((ly & 1) << 1) | (lx & 1);
        g_xp[pbase + (size_t)ph*PLANE + (oy0 + (ly>>1) + 1)*132 + ox0 + (lx>>1) + 1]
            = f2tf(xs[ly + 1][lx]);
    }

    // depthwise convs: logical col cl = 2*oxl+kx -> phys (cl==0 ? 64 : cl-1)
    float wqr[9], war[9];
#pragma unroll
    for (int i = 0; i < 9; i++) { wqr[i] = wq[c*9+i]; war[i] = wadw[c*9+i]; }
#pragma unroll
    for (int j = 0; j < 4; j++) {
        int oyl = (tid >> 5) + j*8, oxl = tid & 31;
#pragma unroll
        for (int dummy = 0; dummy < 1; dummy++) {}
        float aq = 0.f, aa = 0.f;
#pragma unroll
        for (int ky = 0; ky < 3; ky++)
#pragma unroll
            for (int kx = 0; kx < 3; kx++) {
                int cl = 2*oxl + kx;
                float v = (cl == 0) ? xs[2*oyl + ky][64] : xs[2*oyl + ky][cl - 1];
                aq = fmaf(wqr[ky*3+kx], v, aq);
                aa = fmaf(war[ky*3+kx], v, aa);
            }
        size_t o = (size_t)bc * NPIX + (oy0 + oyl)*HO + ox0 + oxl;
        g_q[o] = aq;
        g_adw[o] = aa;
    }
}

#define PREP_N 1440
#define ZP_N   (BATCH*C*4)
#define SDQ_N  (16*BATCH*C)
__global__ __launch_bounds__(256) void preproc_kernel(const float* __restrict__ x,
                                                      const float* __restrict__ wq,
                                                      const float* __restrict__ wadw,
                                                      const float* __restrict__ wk,
                                                      const float* __restrict__ wv)
{
    int bid = blockIdx.x;
    if (bid < SDQ_N)               sdq_body(bid, x, wq, wadw);
    else if (bid < SDQ_N + ZP_N)   zeropad_body(bid - SDQ_N);
    else                           prep_body(bid - SDQ_N - ZP_N, wk, wv);
}

// ================= kconv body: pipelined tf32 implicit GEMM =================
__device__ __forceinline__ void kconv_fillB(unsigned* dstBase, const int* rowoff,
                                            int k0, int tid)
{
    for (int i = tid; i < 1024; i += 256) {
        int kk = i >> 5, g4 = i & 31;
        int pr = g4 >> 2, pc = (g4 & 3) * 4;
        int ro = rowoff[k0 + kk];
        const unsigned* gp = &g_xp[ro + pr*132 + pc];
        unsigned* sp = &dstBase[kk*136 + pr*16 + pc];
        if ((ro & 3) == 0) {
            cpa16(sp, gp);
        } else {
            cpa4(sp,     gp);
            cpa4(sp + 1, gp + 1);
            cpa4(sp + 2, gp + 2);
            cpa4(sp + 3, gp + 3);
        }
    }
}

__device__ void kconv_body(int bid)
{
    extern __shared__ unsigned smm[];
    unsigned* Asm = smm;
    unsigned* Bsm = smm + 2*KC_AS;
    int* rowoff = (int*)(smm + 2*KC_AS + 2*KC_BS);

    int b = bid >> 7;
    int tile = bid & 127;
    int oy0 = (tile >> 3) * 8, ox0 = (tile & 7) * 16;
    int tid = threadIdx.x;
    int warp = tid >> 5, lane = tid & 31;
    int wm = warp >> 1, wn = warp & 1;
    int g = lane >> 2, tg = lane & 3;

    for (int k = tid; k < KKDIM; k += 256) {
        int ic = k / 9, t = k - ic*9;
        int ky = t / 3, kx = t - ky*3;
        int py = (ky == 1) ? 0 : 1, px = (kx == 1) ? 0 : 1;
        int dy = (ky == 0) ? 0 : 1, dx = (kx == 0) ? 0 : 1;
        rowoff[k] = ((b*C + ic)*4 + py*2 + px)*PLANE + (oy0+dy)*132 + (ox0+dx);
    }
    __syncthreads();

    float acc[3][8][4];
#pragma unroll
    for (int mf = 0; mf < 3; mf++)
#pragma unroll
        for (int nf = 0; nf < 8; nf++)
#pragma unroll
            for (int q = 0; q < 4; q++) acc[mf][nf][q] = 0.f;

    for (int i = tid; i < 1536; i += 256) {
        int kk = i / 48, m4 = (i % 48) * 4;
        cpa16(&Asm[kk*200 + m4], &g_wkT[kk*C + m4]);
    }
    kconv_fillB(Bsm, rowoff, 0, tid);
    CP_COMMIT;

#pragma unroll 1
    for (int c2 = 0; c2 < 54; c2++) {
        int p = c2 & 1;
        if (c2 + 1 < 54) {
            int q2 = p ^ 1;
            int k0 = (c2 + 1) * 32;
            for (int i = tid; i < 1536; i += 256) {
                int kk = i / 48, m4 = (i % 48) * 4;
                cpa16(&Asm[q2*KC_AS + kk*200 + m4], &g_wkT[(k0+kk)*C + m4]);
            }
            kconv_fillB(&Bsm[q2*KC_BS], rowoff, k0, tid);
            CP_COMMIT;
            asm volatile("cp.async.wait_group 1;");
        } else {
            asm volatile("cp.async.wait_group 0;");
        }
        __syncthreads();

        const unsigned* Ab = &Asm[p*KC_AS];
        const unsigned* Bb = &Bsm[p*KC_BS];
#pragma unroll
        for (int k8 = 0; k8 < 4; k8++) {
            int kb = k8 * 8;
            unsigned a[3][4], bb[8][2];
#pragma unroll
            for (int mf = 0; mf < 3; mf++) {
                int mb = wm*48 + mf*16 + g;
                a[mf][0] = Ab[(kb+tg)*200 + mb];     a[mf][1] = Ab[(kb+tg)*200 + mb + 8];
                a[mf][2] = Ab[(kb+tg+4)*200 + mb];   a[mf][3] = Ab[(kb+tg+4)*200 + mb + 8];
            }
#pragma unroll
            for (int nf = 0; nf < 8; nf++) {
                int nb = wn*64 + nf*8 + g;
                bb[nf][0] = Bb[(kb+tg)*136 + nb];    bb[nf][1] = Bb[(kb+tg+4)*136 + nb];
            }
#pragma unroll
            for (int mf = 0; mf < 3; mf++)
#pragma unroll
                for (int nf = 0; nf < 8; nf++)
                    mma_tf32(acc[mf][nf][0], acc[mf][nf][1], acc[mf][nf][2], acc[mf][nf][3],
                             a[mf][0], a[mf][1], a[mf][2], a[mf][3], bb[nf][0], bb[nf][1]);
        }
        __syncthreads();
    }

#pragma unroll
    for (int mf = 0; mf < 3; mf++)
#pragma unroll
        for (int nf = 0; nf < 8; nf++) {
            int m = wm*48 + mf*16 + g;
            int n = wn*64 + nf*8 + tg*2;
            int oy = oy0 + (n >> 4), ox = ox0 + (n & 15);
            *(float2*)&g_k[(size_t)(b*C + m)*NPIX + oy*HO + ox] =
                make_float2(acc[mf][nf][0], acc[mf][nf][1]);
            *(float2*)&g_k[(size_t)(b*C + m + 8)*NPIX + oy*HO + ox] =
                make_float2(acc[mf][nf][2], acc[mf][nf][3]);
        }
}

// ================= tgemm body: M=192 x N=128, K=192 =========================
template<int MODE>
__device__ void tgemm_body(int bid, const float* __restrict__ xin,
                           const float* __restrict__ illu,
                           float* __restrict__ outp)
{
    extern __shared__ unsigned smm[];
    unsigned* Asm = smm;
    unsigned* Bsm = smm + 2*KC_AS;

    int b = bid >> 9;
    int n0 = (bid & 511) * 128;
    const unsigned* A = (MODE == 0) ? g_wvT : (g_weffT + (size_t)b*C*C);
    const float* Bf = (MODE == 0) ? (xin + (size_t)b*C*NPIXF) : nullptr;
    const unsigned* Bu = (MODE == 1) ? (g_v + (size_t)b*C*NPIXF) : nullptr;
    const float* Ib = (MODE == 0) ? (illu + (size_t)b*C*NPIXF) : nullptr;

    int tid = threadIdx.x;
    int warp = tid >> 5, lane = tid & 31;
    int wm = warp >> 1, wn = warp & 1;
    int g = lane >> 2, tg = lane & 3;

    float acc[3][8][4];
#pragma unroll
    for (int mf = 0; mf < 3; mf++)
#pragma unroll
        for (int nf = 0; nf < 8; nf++)
#pragma unroll
            for (int q = 0; q < 4; q++) acc[mf][nf][q] = 0.f;

    for (int i = tid; i < 1536; i += 256) {
        int kk = i / 48, m4 = (i % 48) * 4;
        cpa16(&Asm[kk*200 + m4], &A[kk*C + m4]);
    }
    if (MODE == 1) {
        for (int j = 0; j < 4; j++) {
            int i = tid + j*256;
            int kk = i >> 5, n4 = (i & 31) * 4;
            cpa16(&Bsm[kk*136 + n4], &Bu[(size_t)kk*NPIXF + n0 + n4]);
        }
    }
    CP_COMMIT;
    if (MODE == 0) {
        float4 t0[4];
#pragma unroll
        for (int j = 0; j < 4; j++) {
            int i = tid + j*256;
            int kk = i >> 5, n4 = (i & 31) * 4;
            t0[j] = *(const float4*)&Bf[(size_t)kk*NPIXF + n0 + n4];
        }
#pragma unroll
        for (int j = 0; j < 4; j++) {
            int i = tid + j*256;
            int kk = i >> 5, n4 = (i & 31) * 4;
            *(uint4*)&Bsm[kk*136 + n4] =
                make_uint4(f2tf(t0[j].x), f2tf(t0[j].y), f2tf(t0[j].z), f2tf(t0[j].w));
        }
    }

    float4 tmp[4];
#pragma unroll 1
    for (int c2 = 0; c2 < 6; c2++) {
        int p = c2 & 1;
        int q2 = p ^ 1;
        if (c2 + 1 < 6) {
            int k0 = (c2 + 1) * 32;
            for (int i = tid; i < 1536; i += 256) {
                int kk = i / 48, m4 = (i % 48) * 4;
                cpa16(&Asm[q2*KC_AS + kk*200 + m4], &A[(k0+kk)*C + m4]);
            }
            if (MODE == 1) {
#pragma unroll
                for (int j = 0; j < 4; j++) {
                    int i = tid + j*256;
                    int kk = i >> 5, n4 = (i & 31) * 4;
                    cpa16(&Bsm[q2*KC_BS + kk*136 + n4],
                          &Bu[(size_t)(k0+kk)*NPIXF + n0 + n4]);
                }
            }
            CP_COMMIT;
            if (MODE == 0) {
#pragma unroll
                for (int j = 0; j < 4; j++) {
                    int i = tid + j*256;
                    int kk = i >> 5, n4 = (i & 31) * 4;
                    tmp[j] = *(const float4*)&Bf[(size_t)(k0+kk)*NPIXF + n0 + n4];
                }
            }
            asm volatile("cp.async.wait_group 1;");
        } else {
            asm volatile("cp.async.wait_group 0;");
        }
        __syncthreads();

        const unsigned* Ab = &Asm[p*KC_AS];
        const unsigned* Bb = &Bsm[p*KC_BS];
#pragma unroll
        for (int k8 = 0; k8 < 4; k8++) {
            int kb = k8 * 8;
            unsigned a[3][4], bb[8][2];
#pragma unroll
            for (int mf = 0; mf < 3; mf++) {
                int mb = wm*48 + mf*16 + g;
                a[mf][0] = Ab[(kb+tg)*200 + mb];     a[mf][1] = Ab[(kb+tg)*200 + mb + 8];
                a[mf][2] = Ab[(kb+tg+4)*200 + mb];   a[mf][3] = Ab[(kb+tg+4)*200 + mb + 8];
            }
#pragma unroll
            for (int nf = 0; nf < 8; nf++) {
                int nb = wn*64 + nf*8 + g;
                bb[nf][0] = Bb[(kb+tg)*136 + nb];    bb[nf][1] = Bb[(kb+tg+4)*136 + nb];
            }
#pragma unroll
            for (int mf = 0; mf < 3; mf++)
#pragma unroll
                for (int nf = 0; nf < 8; nf++)
                    mma_tf32(acc[mf][nf][0], acc[mf][nf][1], acc[mf][nf][2], acc[mf][nf][3],
                             a[mf][0], a[mf][1], a[mf][2], a[mf][3], bb[nf][0], bb[nf][1]);
        }
        if (MODE == 0 && c2 + 1 < 6) {
#pragma unroll
            for (int j = 0; j < 4; j++) {
                int i = tid + j*256;
                int kk = i >> 5, n4 = (i & 31) * 4;
                *(uint4*)&Bsm[q2*KC_BS + kk*136 + n4] =
                    make_uint4(f2tf(tmp[j].x), f2tf(tmp[j].y), f2tf(tmp[j].z), f2tf(tmp[j].w));
            }
        }
        __syncthreads();
    }

#pragma unroll
    for (int mf = 0; mf < 3; mf++)
#pragma unroll
        for (int nf = 0; nf < 8; nf++) {
            int m = wm*48 + mf*16 + g;
            int n = n0 + wn*64 + nf*8 + tg*2;
            if (MODE == 0) {
                float2 i0 = *(const float2*)&Ib[(size_t)m*NPIXF + n];
                float2 i1 = *(const float2*)&Ib[(size_t)(m+8)*NPIXF + n];
                unsigned* O = g_v + (size_t)b*C*NPIXF;
                *(uint2*)&O[(size_t)m*NPIXF + n] =
                    make_uint2(f2tf(acc[mf][nf][0]*i0.x), f2tf(acc[mf][nf][1]*i0.y));
                *(uint2*)&O[(size_t)(m+8)*NPIXF + n] =
                    make_uint2(f2tf(acc[mf][nf][2]*i1.x), f2tf(acc[mf][nf][3]*i1.y));
            } else {
                float* O = outp + (size_t)b*C*NPIXF;
                *(float2*)&O[(size_t)m*NPIXF + n] =
                    make_float2(acc[mf][nf][0], acc[mf][nf][1]);
                *(float2*)&O[(size_t)(m+8)*NPIXF + n] =
                    make_float2(acc[mf][nf][2], acc[mf][nf][3]);
            }
        }
}

// ================= apw body: pointwise 192->96 (+bias) ======================
__device__ void apw_body(int bid, const float* __restrict__ wapw,
                         const float* __restrict__ bapw)
{
    extern __shared__ unsigned smm[];
    float* s = (float*)smm;               // C*64 floats = 48KB
    int b = bid >> 8;
    int p0 = (bid & 255) * 64;
    for (int i = threadIdx.x; i < C*64; i += 256) {
        int cc = i >> 6, pp = i & 63;
        s[i] = g_adw[(size_t)(b*C + cc)*NPIX + p0 + pp];
    }
    __syncthreads();
    int pg  = threadIdx.x & 15;
    int ocb = threadIdx.x >> 4;
    for (int oc = ocb; oc < CA; oc += 16) {
        float bsv = bapw[oc];
        float4 acc = make_float4(bsv, bsv, bsv, bsv);
        for (int ic = 0; ic < C; ic++) {
            float w = __ldg(&wapw[oc*C + ic]);
            float4 xv = *reinterpret_cast<const float4*>(&s[ic*64 + pg*4]);
            acc.x = fmaf(w, xv.x, acc.x);
            acc.y = fmaf(w, xv.y, acc.y);
            acc.z = fmaf(w, xv.z, acc.z);
            acc.w = fmaf(w, xv.w, acc.w);
        }
        *reinterpret_cast<float4*>(&g_a[(size_t)(b*CA + oc)*NPIX + p0 + pg*4]) = acc;
    }
}

// ================= fat kernel: kconv + tgemm0 + apw =========================
#define KCONV_N 512
#define TG0_N   2048
#define APW_N   1024
__global__ __launch_bounds__(256) void fat_kernel(const float* __restrict__ x,
                                                  const float* __restrict__ illu,
                                                  const float* __restrict__ wapw,
                                                  const float* __restrict__ bapw)
{
    int bid = blockIdx.x;
    if (bid < KCONV_N)            kconv_body(bid);
    else if (bid < KCONV_N+TG0_N) tgemm_body<0>(bid - KCONV_N, x, illu, nullptr);
    else                          apw_body(bid - KCONV_N - TG0_N, wapw, bapw);
}

__global__ __launch_bounds__(256) void tgemm1_kernel(float* __restrict__ outp)
{
    tgemm_body<1>(blockIdx.x, nullptr, nullptr, outp);
}

// ================= attention dots + fused norms =============================
__global__ __launch_bounds__(768) void attn_kernel()
{
    __shared__ float a_s[CAH][256];
    int split = blockIdx.x, bh = blockIdx.y;
    int b = bh >> 3, h = bh & 7;
    int tid = threadIdx.x, warp = tid >> 5, lane = tid & 31;
    const float* qp = g_q + (size_t)(b*C + h*CQH + warp)*NPIX;
    const float* kp = g_k + (size_t)(b*C + h*CQH + warp)*NPIX;
    const float* ap = g_a + (size_t)(b*CA + h*CAH)*NPIX;
    int p0 = split * (NPIX / NSPLIT);

    float dq[12], dk[12];
#pragma unroll
    for (int d = 0; d < 12; d++) { dq[d] = 0.f; dk[d] = 0.f; }
    float qq = 0.f, kk = 0.f, aa = 0.f;

    for (int c0 = 0; c0 < NPIX/NSPLIT; c0 += 256) {
        for (int i = tid; i < CAH*256; i += 768) {
            int d = i >> 8, p = i & 255;
            a_s[d][p] = ap[(size_t)d*NPIX + p0 + c0 + p];
        }
        __syncthreads();
#pragma unroll
        for (int hf = 0; hf < 2; hf++) {
            int p = hf*128 + lane*4;
            float4 qv = *(const float4*)&qp[p0 + c0 + p];
            float4 kv = *(const float4*)&kp[p0 + c0 + p];
            qq += qv.x*qv.x + qv.y*qv.y + qv.z*qv.z + qv.w*qv.w;
            kk += kv.x*kv.x + kv.y*kv.y + kv.z*kv.z + kv.w*kv.w;
            if (warp < CAH) {
                float4 av = *(const float4*)&a_s[warp][p];
                aa += av.x*av.x + av.y*av.y + av.z*av.z + av.w*av.w;
            }
#pragma unroll
            for (int d = 0; d < 12; d++) {
                float4 av = *(const float4*)&a_s[d][p];
                dq[d] += qv.x*av.x + qv.y*av.y + qv.z*av.z + qv.w*av.w;
                dk[d] += kv.x*av.x + kv.y*av.y + kv.z*av.z + kv.w*av.w;
            }
        }
        __syncthreads();
    }
#pragma unroll
    for (int off = 16; off; off >>= 1) {
#pragma unroll
        for (int d = 0; d < 12; d++) {
            dq[d] += __shfl_down_sync(0xffffffffu, dq[d], off);
            dk[d] += __shfl_down_sync(0xffffffffu, dk[d], off);
        }
        qq += __shfl_down_sync(0xffffffffu, qq, off);
        kk += __shfl_down_sync(0xffffffffu, kk, off);
        aa += __shfl_down_sync(0xffffffffu, aa, off);
    }
    if (lane == 0) {
        float* out = &g_dotp[((size_t)split*BATCH*HEADS + bh)*DOTP];
#pragma unroll
        for (int d = 0; d < 12; d++) {
            out[warp*12 + d]       = dq[d];
            out[288 + warp*12 + d] = dk[d];
        }
        out[576 + warp] = qq;
        out[600 + warp] = kk;
        if (warp < 12) out[624 + warp] = aa;
    }
}

// ================= combine: norms, softmax, M, W_eff^T slice (tf32) =========
// grid (64, BATCH): every block redundantly computes softmax+M (cheap),
// then writes a 1/64 slice of W_eff^T -> 256 active blocks.
#define WSLICE (C*C/64)      // 576
__global__ __launch_bounds__(256) void combine_kernel(const float* __restrict__ wo,
                                                      const float* __restrict__ ta,
                                                      const float* __restrict__ tv)
{
    __shared__ float buf[HEADS*DOTP];
    __shared__ float SA[HEADS][CQH][CAH];
    __shared__ float SK[HEADS][CAH][CQH];
    int slice = blockIdx.x, b = blockIdx.y, tid = threadIdx.x;

    for (int i = tid; i < HEADS*DOTP; i += 256) {
        int h = i / DOTP, e = i - h*DOTP;
        float s = 0.f;
#pragma unroll
        for (int sp = 0; sp < NSPLIT; sp++)
            s += g_dotp[((size_t)sp*BATCH*HEADS + b*HEADS + h)*DOTP + e];
        buf[i] = s;
    }
    __syncthreads();

    if (tid < HEADS*CQH) {
        int h = tid / CQH, c = tid % CQH;
        const float* B = &buf[h*DOTP];
        float invq = 1.f / fmaxf(sqrtf(B[576 + c]), 1e-12f);
        float tah = ta[h];
        float l[CAH], m = -1e30f;
#pragma unroll
        for (int d = 0; d < CAH; d++) {
            float inva = 1.f / fmaxf(sqrtf(B[624 + d]), 1e-12f);
            l[d] = B[c*12 + d] * invq * inva * tah;
            m = fmaxf(m, l[d]);
        }
        float s = 0.f;
#pragma unroll
        for (int d = 0; d < CAH; d++) { l[d] = expf(l[d] - m); s += l[d]; }
        float inv = 1.f / s;
#pragma unroll
        for (int d = 0; d < CAH; d++) SA[h][c][d] = l[d] * inv;
    }
    if (tid < HEADS*CAH) {
        int h = tid / CAH, d = tid % CAH;
        const float* B = &buf[h*DOTP];
        float inva = 1.f / fmaxf(sqrtf(B[624 + d]), 1e-12f);
        float tvh = tv[h];
        float l[CQH], m = -1e30f;
#pragma unroll
        for (int c = 0; c < CQH; c++) {
            float invk = 1.f / fmaxf(sqrtf(B[600 + c]), 1e-12f);
            l[c] = B[288 + c*12 + d] * invk * inva * tvh;
            m = fmaxf(m, l[c]);
        }
        float s = 0.f;
#pragma unroll
        for (int c = 0; c < CQH; c++) { l[c] = expf(l[c] - m); s += l[c]; }
        float inv = 1.f / s;
#pragma unroll
        for (int c = 0; c < CQH; c++) SK[h][d][c] = l[c] * inv;
    }
    __syncthreads();

    float* M = buf;
    for (int i = tid; i < HEADS*CQH*CQH; i += 256) {
        int h = i / (CQH*CQH), r = (i / CQH) % CQH, j = i % CQH;
        float s = 0.f;
#pragma unroll
        for (int d = 0; d < CAH; d++) s = fmaf(SA[h][r][d], SK[h][d][j], s);
        M[(h*CQH + r)*CQH + j] = s;
    }
    __syncthreads();

    // this block's 1/64 slice of W_eff^T ([cv][o] layout)
    int base = slice * WSLICE;
    for (int i = base + tid; i < base + WSLICE; i += 256) {
        int cv = i / C, o = i % C;
        int hv = cv / CQH, j = cv % CQH;
        float s = 0.f;
#pragma unroll
        for (int k = 0; k < CQH; k++)
            s = fmaf(wo[o*C + hv*CQH + k], M[(hv*CQH + k)*CQH + j], s);
        g_weffT[(size_t)b*C*C + i] = f2tf(s);
    }
}

// ================= launch ===================================================
extern "C" void kernel_launch(void* const* d_in, const int* in_sizes, int n_in,
                              void* d_out, int out_size)
{
    const float* x    = (const float*)d_in[0];
    const float* illu = (const float*)d_in[1];
    const float* wq   = (const float*)d_in[2];
    const float* wk   = (const float*)d_in[3];
    const float* wadw = (const float*)d_in[4];
    const float* wapw = (const float*)d_in[5];
    const float* bapw = (const float*)d_in[6];
    const float* wv   = (const float*)d_in[7];
    const float* wo   = (const float*)d_in[8];
    const float* ta   = (const float*)d_in[9];
    const float* tv   = (const float*)d_in[10];
    float* out = (float*)d_out;

    const int fat_smem = (2*KC_AS + 2*KC_BS + KKDIM) * 4;   // 92928
    const int tg_smem  = (2*KC_AS + 2*KC_BS) * 4;           // 86016
    cudaFuncSetAttribute(fat_kernel, cudaFuncAttributeMaxDynamicSharedMemorySize, fat_smem);
    cudaFuncSetAttribute(tgemm1_kernel, cudaFuncAttributeMaxDynamicSharedMemorySize, tg_smem);

    preproc_kernel<<<SDQ_N + ZP_N + PREP_N, 256>>>(x, wq, wadw, wk, wv);
    fat_kernel    <<<KCONV_N + TG0_N + APW_N, 256, fat_smem>>>(x, illu, wapw, bapw);
    attn_kernel   <<<dim3(NSPLIT, BATCH*HEADS), 768>>>();
    combine_kernel<<<dim3(64, BATCH), 256>>>(wo, ta, tv);
    tgemm1_kernel <<<TG0_N, 256, tg_smem>>>(out);
}